// round 8
// baseline (speedup 1.0000x reference)
#include <cuda_runtime.h>
#include <cuda_bf16.h>
#include <math.h>

// Problem constants
#define BB 64
#define HH 1024
#define EE 512
#define VV 32000
#define TENC 64
#define STEPS 32
#define KOUT 2048   // 2*H

typedef unsigned long long ull;
typedef unsigned int u32;

// ---------------- scratch (device globals; no allocation allowed) ----------
__device__ float g_a0[BB * 192];
__device__ float g_h[BB * HH];            // fp32 master hidden state
__device__ float g_gip[2][BB * 3 * HH];   // split-K partials of x @ W_ih^T
__device__ float g_ghp[2][BB * 3 * HH];   // split-K partials of h @ W_hh^T
__device__ float g_qp[4][BB * HH];        // split-K partials of h @ W_a

// split-bf16 activations (16B-aligned for cp.async)
__device__ __align__(16) __nv_bfloat16 g_xh[BB * EE],  g_xl[BB * EE];
__device__ __align__(16) __nv_bfloat16 g_hbh[BB * HH], g_hbl[BB * HH];
__device__ __align__(16) __nv_bfloat16 g_vch[BB * KOUT], g_vcl[BB * KOUT];

// split-bf16 weights, all stored [N, K] row-major
__device__ __align__(16) __nv_bfloat16 g_Wihh[3 * HH * EE], g_Wihl[3 * HH * EE];
__device__ __align__(16) __nv_bfloat16 g_Whhh[3 * HH * HH], g_Whhl[3 * HH * HH];
__device__ __align__(16) __nv_bfloat16 g_Wah[HH * HH],      g_Wal[HH * HH];
__device__ __align__(16) __nv_bfloat16 g_Wouth[(size_t)VV * KOUT];
__device__ __align__(16) __nv_bfloat16 g_Woutl[(size_t)VV * KOUT];

// ====================== PTX helpers ========================================
__device__ __forceinline__ u32 smem_u32(const void* p) {
    u32 a;
    asm("{ .reg .u64 t; cvta.to.shared.u64 t, %1; cvt.u32.u64 %0, t; }"
        : "=r"(a) : "l"(p));
    return a;
}
__device__ __forceinline__ void cp16(u32 dst, const void* src) {
    asm volatile("cp.async.cg.shared.global [%0], [%1], 16;"
                 :: "r"(dst), "l"(src) : "memory");
}
__device__ __forceinline__ void cp_commit() {
    asm volatile("cp.async.commit_group;" ::: "memory");
}
__device__ __forceinline__ void cp_wait2() {
    asm volatile("cp.async.wait_group 2;" ::: "memory");
}
__device__ __forceinline__ void ldmx4(u32* r, u32 addr) {
    asm volatile("ldmatrix.sync.aligned.m8n8.x4.shared.b16 {%0,%1,%2,%3}, [%4];"
                 : "=r"(r[0]), "=r"(r[1]), "=r"(r[2]), "=r"(r[3]) : "r"(addr));
}
__device__ __forceinline__ void mma16816(float* c, const u32* a, const u32* b) {
    asm volatile(
        "mma.sync.aligned.m16n8k16.row.col.f32.bf16.bf16.f32 "
        "{%0,%1,%2,%3}, {%4,%5,%6,%7}, {%8,%9}, {%0,%1,%2,%3};"
        : "+f"(c[0]), "+f"(c[1]), "+f"(c[2]), "+f"(c[3])
        : "r"(a[0]), "r"(a[1]), "r"(a[2]), "r"(a[3]), "r"(b[0]), "r"(b[1]));
}

// ===========================================================================
// Split-bf16 HMMA GEMM body:
//   C[64, N] = (Ah+Al)[64,Klen] @ (Bh+Bl)[N,Klen]^T (+ bias)
//   = Ah·Bh + Al·Bh + Ah·Bl  (Al·Bl dropped, ~2^-16 relative)
// Rows of A and B stride by ldk elements (for split-K, pointers pre-offset).
// CTA tile 64 x NT, 256 threads (8 warps, warp tile 32 x NT/4).
// K-chunks of 32, cp.async 3-stage pipeline. Klen%32==0, Klen>=96.
// ===========================================================================
template <int NT>
__device__ __forceinline__ void load_chunk(
    u32 sb, const __nv_bfloat16* Ah, const __nv_bfloat16* Al,
    const __nv_bfloat16* Bh, const __nv_bfloat16* Bl,
    int n0, int ldk, int k0, int tid)
{
    const int OFF_AL = 64 * 80, OFF_BH = 128 * 80, OFF_BL = OFF_BH + NT * 80;
#pragma unroll
    for (int r = 0; r < 2; r++) {
        int i = tid + r * 256;
        int seg = i & 3, row = (i >> 2) & 63, hi = i >> 8;
        const __nv_bfloat16* src = (hi ? Al : Ah) + (size_t)row * ldk + k0 + seg * 8;
        cp16(sb + (hi ? OFF_AL : 0) + row * 80 + seg * 16, src);
    }
#pragma unroll
    for (int r = 0; r < NT / 32; r++) {
        int i = tid + r * 256;
        int seg = i & 3, row = (i >> 2) & (NT - 1);
        int hi = (i >= NT * 4);
        const __nv_bfloat16* src = (hi ? Bl : Bh) + (size_t)(n0 + row) * ldk + k0 + seg * 8;
        cp16(sb + (hi ? OFF_BL : OFF_BH) + row * 80 + seg * 16, src);
    }
}

template <int NT>
__device__ __forceinline__ void gemm_body(
    const __nv_bfloat16* __restrict__ Ah, const __nv_bfloat16* __restrict__ Al,
    const __nv_bfloat16* __restrict__ Bh, const __nv_bfloat16* __restrict__ Bl,
    const float* __restrict__ bias, float* __restrict__ C,
    long ldc, int Klen, int ldk, int n_cta, char* smem)
{
    const int BUFSZ = 80 * (128 + 2 * NT);
    const int OFF_BH = 128 * 80, OFF_BL = OFF_BH + NT * 80;
    const int NPW = NT / 4, NPAIR = NPW / 16;
    const u32 sb = smem_u32(smem);
    const int tid = threadIdx.x, wid = tid >> 5, lane = tid & 31;
    const int wm = (wid >> 2) * 32;
    const int wn = (wid & 3) * NPW;

    float acc[2][2 * NPAIR][4] = {};

    const int nk = Klen >> 5;
    load_chunk<NT>(sb,         Ah, Al, Bh, Bl, n_cta, ldk, 0,  tid); cp_commit();
    load_chunk<NT>(sb + BUFSZ, Ah, Al, Bh, Bl, n_cta, ldk, 32, tid); cp_commit();

    const int lrow = lane & 15;
    const int lkof = (lane >> 4) * 16;

    for (int i = 0; i < nk; i++) {
        if (i + 2 < nk)
            load_chunk<NT>(sb + ((i + 2) % 3) * BUFSZ, Ah, Al, Bh, Bl,
                           n_cta, ldk, (i + 2) * 32, tid);
        cp_commit();
        cp_wait2();
        __syncthreads();

        const u32 bb = sb + (i % 3) * BUFSZ;
#pragma unroll
        for (int ks = 0; ks < 2; ks++) {
            const u32 kb = ks * 32 + lkof;
            u32 ah[2][4], al[2][4], bh[NPAIR][4], bl[NPAIR][4];
            ldmx4(ah[0], bb + (wm + lrow) * 80 + kb);
            ldmx4(ah[1], bb + (wm + 16 + lrow) * 80 + kb);
            ldmx4(al[0], bb + 5120 + (wm + lrow) * 80 + kb);
            ldmx4(al[1], bb + 5120 + (wm + 16 + lrow) * 80 + kb);
#pragma unroll
            for (int p = 0; p < NPAIR; p++) {
                ldmx4(bh[p], bb + OFF_BH + (wn + p * 16 + lrow) * 80 + kb);
                ldmx4(bl[p], bb + OFF_BL + (wn + p * 16 + lrow) * 80 + kb);
            }
#pragma unroll
            for (int mt = 0; mt < 2; mt++) {
#pragma unroll
                for (int p = 0; p < NPAIR; p++) {
                    u32 b0h[2] = { bh[p][0], bh[p][2] };
                    u32 b1h[2] = { bh[p][1], bh[p][3] };
                    u32 b0l[2] = { bl[p][0], bl[p][2] };
                    u32 b1l[2] = { bl[p][1], bl[p][3] };
                    float* c0 = acc[mt][p * 2];
                    float* c1 = acc[mt][p * 2 + 1];
                    mma16816(c0, ah[mt], b0h);
                    mma16816(c1, ah[mt], b1h);
                    mma16816(c0, al[mt], b0h);
                    mma16816(c1, al[mt], b1h);
                    mma16816(c0, ah[mt], b0l);
                    mma16816(c1, ah[mt], b1l);
                }
            }
        }
        __syncthreads();
    }

#pragma unroll
    for (int mt = 0; mt < 2; mt++) {
        int m = wm + mt * 16 + (lane >> 2);
#pragma unroll
        for (int p = 0; p < NPAIR; p++) {
#pragma unroll
            for (int t = 0; t < 2; t++) {
                int n = n_cta + wn + p * 16 + t * 8 + 2 * (lane & 3);
                float* a = acc[mt][p * 2 + t];
                float b0 = bias ? bias[n] : 0.f;
                float b1 = bias ? bias[n + 1] : 0.f;
                float2 v0 = { a[0] + b0, a[1] + b1 };
                float2 v1 = { a[2] + b0, a[3] + b1 };
                *reinterpret_cast<float2*>(C + (size_t)m * ldc + n) = v0;
                *reinterpret_cast<float2*>(C + (size_t)(m + 8) * ldc + n) = v1;
            }
        }
    }
}

// logits GEMM: NT=256, full K
__global__ __launch_bounds__(256)
void gemm_logits(const __nv_bfloat16* __restrict__ Ah, const __nv_bfloat16* __restrict__ Al,
                 const __nv_bfloat16* __restrict__ Bh, const __nv_bfloat16* __restrict__ Bl,
                 const float* __restrict__ bias, float* __restrict__ C, long ldc)
{
    extern __shared__ char smem[];
    gemm_body<256>(Ah, Al, Bh, Bl, bias, C, ldc, KOUT, KOUT, blockIdx.x * 256, smem);
}

// q-GEMM 4-way split-K: 32 CTAs; slice s covers k in [s*256, (s+1)*256)
__global__ __launch_bounds__(256)
void gemm_q(const __nv_bfloat16* __restrict__ hbh, const __nv_bfloat16* __restrict__ hbl,
            const __nv_bfloat16* __restrict__ Wah, const __nv_bfloat16* __restrict__ Wal)
{
    extern __shared__ char smem[];
    int s = blockIdx.x >> 3, nt = blockIdx.x & 7;
    int k0 = s * 256;
    gemm_body<128>(hbh + k0, hbl + k0, Wah + k0, Wal + k0, nullptr,
                   g_qp[s], HH, 256, HH, nt * 128, smem);
}

// fused gi + gh, each 2-way split-K: 96 CTAs
//  bid in [0,48): gi, slice = bid/24 (K=512 -> 2x256)
//  bid in [48,96): gh, slice = (bid-48)/24 (K=1024 -> 2x512)
__global__ __launch_bounds__(256)
void gemm_gigh(const __nv_bfloat16* __restrict__ xh, const __nv_bfloat16* __restrict__ xl,
               const __nv_bfloat16* __restrict__ Wihh, const __nv_bfloat16* __restrict__ Wihl,
               const __nv_bfloat16* __restrict__ hbh, const __nv_bfloat16* __restrict__ hbl,
               const __nv_bfloat16* __restrict__ Whhh, const __nv_bfloat16* __restrict__ Whhl)
{
    extern __shared__ char smem[];
    int bid = blockIdx.x;
    if (bid < 48) {
        int s = bid / 24, nt = bid % 24;
        int k0 = s * 256;
        gemm_body<128>(xh + k0, xl + k0, Wihh + k0, Wihl + k0, nullptr,
                       g_gip[s], 3 * HH, 256, EE, nt * 128, smem);
    } else {
        bid -= 48;
        int s = bid / 24, nt = bid % 24;
        int k0 = s * 512;
        gemm_body<128>(hbh + k0, hbl + k0, Whhh + k0, Whhl + k0, nullptr,
                       g_ghp[s], 3 * HH, 512, HH, nt * 128, smem);
    }
}

#define SMEM_128 (3 * 80 * (128 + 2 * 128))   //  92160
#define SMEM_256 (3 * 80 * (128 + 2 * 256))   // 153600

// ===================== conversion (single fused kernel) ====================
__device__ __forceinline__ void split2(float v, __nv_bfloat16& h, __nv_bfloat16& l) {
    h = __float2bfloat16(v);
    l = __float2bfloat16(v - __bfloat162float(h));
}

__device__ __forceinline__ void esplit_blk(const float* src, __nv_bfloat16* dh,
                                           __nv_bfloat16* dl, int bi, int tid)
{
    int i = bi * 256 + tid;
    split2(src[i], dh[i], dl[i]);
}

// one 32x32 transpose tile: src [K,N] fp32 -> dh/dl [N,K] bf16
__device__ __forceinline__ void tsplit_blk(const float* src, __nv_bfloat16* dh,
                                           __nv_bfloat16* dl, int K, int N,
                                           int bx, int by, int tid)
{
    __shared__ float t[32][33];
    int k0 = by * 32, n0 = bx * 32;
    int tx = tid & 31, ty = tid >> 5;   // 32 x 8
#pragma unroll
    for (int i = ty; i < 32; i += 8)
        t[i][tx] = src[(size_t)(k0 + i) * N + n0 + tx];
    __syncthreads();
#pragma unroll
    for (int i = ty; i < 32; i += 8) {
        float v = t[tx][i];
        __nv_bfloat16 h, l; split2(v, h, l);
        dh[(size_t)(n0 + i) * K + k0 + tx] = h;
        dl[(size_t)(n0 + i) * K + k0 + tx] = l;
    }
}

#define NB_WIH  6144    // 3*HH*EE / 256
#define NB_WHH 12288    // 3*HH*HH / 256
#define NB_WA   1024    // (HH/32)*(HH/32)
#define NB_WOUT 64000   // (VV/32)*(KOUT/32)
#define NB_CONV (NB_WIH + NB_WHH + NB_WA + NB_WOUT)

__global__ __launch_bounds__(256)
void convert_all(const float* __restrict__ W_ih, const float* __restrict__ W_hh,
                 const float* __restrict__ W_a,  const float* __restrict__ W_out)
{
    int b = blockIdx.x, tid = threadIdx.x;
    if (b < NB_WIH) {
        esplit_blk(W_ih, g_Wihh, g_Wihl, b, tid);
    } else if (b < NB_WIH + NB_WHH) {
        esplit_blk(W_hh, g_Whhh, g_Whhl, b - NB_WIH, tid);
    } else if (b < NB_WIH + NB_WHH + NB_WA) {
        int bi = b - NB_WIH - NB_WHH;
        tsplit_blk(W_a, g_Wah, g_Wal, HH, HH, bi % 32, bi / 32, tid);
    } else {
        int bi = b - NB_WIH - NB_WHH - NB_WA;
        tsplit_blk(W_out, g_Wouth, g_Woutl, KOUT, VV, bi % (VV / 32), bi / (VV / 32), tid);
    }
}

// ======================= init kernels ======================================
__global__ void build_init(const float* __restrict__ latent,
                           const int* __restrict__ style,
                           const float* __restrict__ style_emb,
                           const float* __restrict__ emb)
{
    int idx = blockIdx.x * blockDim.x + threadIdx.x;   // 64*192 + 64*512
    if (idx < BB * 192) {
        int b = idx / 192, k = idx - b * 192;
        g_a0[idx] = (k < 128) ? latent[b * 128 + k]
                              : style_emb[style[b] * 64 + (k - 128)];
    } else {
        int i = idx - BB * 192;
        if (i < BB * EE) {
            float v = emb[EE /* BOS=1 row */ + (i & (EE - 1))];
            split2(v, g_xh[i], g_xl[i]);
        }
    }
}

// h = a0 @ W_l2h + b (fp32 FFMA; also emits split-bf16 h)
__global__ __launch_bounds__(128)
void gemm_init(const float* __restrict__ A, int lda,
               const float* __restrict__ Bm, const float* __restrict__ bias,
               float* __restrict__ C, int N, int K)
{
    __shared__ float As[16][68];
    __shared__ float Bs[16][132];
    const int tid = threadIdx.x;
    const int n0 = blockIdx.x * 128;
    const int tm = (tid >> 4) << 3, tn = (tid & 15) << 3;
    float acc[8][8] = {};
    for (int k0 = 0; k0 < K; k0 += 16) {
        {
            int k = tid & 15, m = tid >> 4;
#pragma unroll
            for (int i = 0; i < 8; i++)
                As[k][m + i * 8] = A[(m + i * 8) * lda + k0 + k];
        }
        {
            int w = tid >> 5, n4 = (tid & 31) << 2;
#pragma unroll
            for (int kb = 0; kb < 4; kb++) {
                int k = kb * 4 + w;
                *reinterpret_cast<float4*>(&Bs[k][n4]) =
                    *reinterpret_cast<const float4*>(&Bm[(size_t)(k0 + k) * N + n0 + n4]);
            }
        }
        __syncthreads();
#pragma unroll
        for (int kk = 0; kk < 16; kk++) {
#pragma unroll
            for (int i = 0; i < 8; i++) {
                float a = As[kk][tm + i];
#pragma unroll
                for (int j = 0; j < 8; j++) acc[i][j] += a * Bs[kk][tn + j];
            }
        }
        __syncthreads();
    }
#pragma unroll
    for (int i = 0; i < 8; i++)
#pragma unroll
        for (int j = 0; j < 8; j++) {
            int n = n0 + tn + j;
            float v = acc[i][j] + (bias ? bias[n] : 0.f);
            int idx = (tm + i) * N + n;
            C[idx] = v;
            split2(v, g_hbh[idx], g_hbl[idx]);
        }
}

// ========================= per-step small kernels ==========================
__global__ void gru_gates(const float* __restrict__ b_ih, const float* __restrict__ b_hh)
{
    int idx = blockIdx.x * blockDim.x + threadIdx.x;   // 64*1024
    int b = idx >> 10, j = idx & 1023;
    int base = b * 3 * HH + j;
    float ir = g_gip[0][base]          + g_gip[1][base]          + b_ih[j];
    float iz = g_gip[0][base + HH]     + g_gip[1][base + HH]     + b_ih[j + HH];
    float in = g_gip[0][base + 2 * HH] + g_gip[1][base + 2 * HH] + b_ih[j + 2 * HH];
    float hr = g_ghp[0][base]          + g_ghp[1][base]          + b_hh[j];
    float hz = g_ghp[0][base + HH]     + g_ghp[1][base + HH]     + b_hh[j + HH];
    float hn = g_ghp[0][base + 2 * HH] + g_ghp[1][base + 2 * HH] + b_hh[j + 2 * HH];
    float r = 1.f / (1.f + expf(-(ir + hr)));
    float z = 1.f / (1.f + expf(-(iz + hz)));
    float n = tanhf(in + r * hn);
    float hnew = (1.f - z) * n + z * g_h[idx];
    g_h[idx] = hnew;
    __nv_bfloat16 hh, hl; split2(hnew, hh, hl);
    g_hbh[idx] = hh; g_hbl[idx] = hl;
    g_vch[b * KOUT + j] = hh; g_vcl[b * KOUT + j] = hl;
}

__global__ void attn_kernel(const float* __restrict__ enc)
{
    int b = blockIdx.x;
    int tid = threadIdx.x;              // 256
    __shared__ float s_q[HH];
    __shared__ float s_scores[TENC];
    __shared__ float s_attn[TENC];

    for (int i = tid; i < HH; i += 256) {
        int o = b * HH + i;
        s_q[i] = g_qp[0][o] + g_qp[1][o] + g_qp[2][o] + g_qp[3][o];
    }
    __syncthreads();

    int warp = tid >> 5, lane = tid & 31;
    for (int t = warp; t < TENC; t += 8) {
        const float* e = enc + ((size_t)b * TENC + t) * HH;
        float s = 0.f;
        for (int h = lane; h < HH; h += 32) s += s_q[h] * e[h];
#pragma unroll
        for (int o = 16; o; o >>= 1) s += __shfl_xor_sync(0xFFFFFFFFu, s, o);
        if (lane == 0) s_scores[t] = s;
    }
    __syncthreads();

    float mx = -1e30f;
    for (int t = 0; t < TENC; t++) mx = fmaxf(mx, s_scores[t]);
    if (tid < TENC) s_attn[tid] = expf(s_scores[tid] - mx);
    __syncthreads();
    float ssum = 0.f;
    for (int t = 0; t < TENC; t++) ssum += s_attn[t];
    float inv = 1.f / ssum;

    for (int h = tid; h < HH; h += 256) {
        float c = 0.f;
        const float* eb = enc + (size_t)b * TENC * HH + h;
#pragma unroll 8
        for (int t = 0; t < TENC; t++) c += s_attn[t] * eb[(size_t)t * HH];
        c *= inv;
        __nv_bfloat16 ch, cl; split2(c, ch, cl);
        g_vch[b * KOUT + HH + h] = ch;
        g_vcl[b * KOUT + HH + h] = cl;
    }
}

__global__ void argmax_embed(const float* __restrict__ logits_t,
                             const float* __restrict__ emb)
{
    int b = blockIdx.x;
    int tid = threadIdx.x;              // 256
    const float* L = logits_t + (size_t)b * STEPS * VV;

    float best = -1e30f; int bi = VV;
    for (int n = tid; n < VV; n += 256) {
        float v = L[n];
        if (v > best) { best = v; bi = n; }
    }
    __shared__ float sv[256]; __shared__ int si[256];
    sv[tid] = best; si[tid] = bi;
    __syncthreads();
    for (int s = 128; s; s >>= 1) {
        if (tid < s) {
            if (sv[tid + s] > sv[tid] ||
                (sv[tid + s] == sv[tid] && si[tid + s] < si[tid])) {
                sv[tid] = sv[tid + s]; si[tid] = si[tid + s];
            }
        }
        __syncthreads();
    }
    int tok = si[0];
    for (int e = tid; e < EE; e += 256) {
        float v = emb[(size_t)tok * EE + e];
        split2(v, g_xh[b * EE + e], g_xl[b * EE + e]);
    }
}

// ===========================================================================
extern "C" void kernel_launch(void* const* d_in, const int* in_sizes, int n_in,
                              void* d_out, int out_size)
{
    const float* latent    = (const float*)d_in[0];
    const int*   style     = (const int*)  d_in[1];
    const float* enc       = (const float*)d_in[2];
    const float* emb       = (const float*)d_in[4];
    const float* style_emb = (const float*)d_in[5];
    const float* W_l2h     = (const float*)d_in[6];
    const float* b_l2h     = (const float*)d_in[7];
    const float* W_ih      = (const float*)d_in[8];
    const float* W_hh      = (const float*)d_in[9];
    const float* b_ih      = (const float*)d_in[10];
    const float* b_hh      = (const float*)d_in[11];
    const float* W_a       = (const float*)d_in[12];
    const float* W_out     = (const float*)d_in[13];
    const float* b_out     = (const float*)d_in[14];
    float* out = (float*)d_out;

    cudaFuncSetAttribute(gemm_logits, cudaFuncAttributeMaxDynamicSharedMemorySize, SMEM_256);
    cudaFuncSetAttribute(gemm_q,      cudaFuncAttributeMaxDynamicSharedMemorySize, SMEM_128);
    cudaFuncSetAttribute(gemm_gigh,   cudaFuncAttributeMaxDynamicSharedMemorySize, SMEM_128);

    __nv_bfloat16 *pWihh, *pWihl, *pWhhh, *pWhhl, *pWah, *pWal, *pWouth, *pWoutl;
    __nv_bfloat16 *pxh, *pxl, *phbh, *phbl, *pvch, *pvcl;
    float *p_a0, *p_h;
    cudaGetSymbolAddress((void**)&pWihh, g_Wihh);   cudaGetSymbolAddress((void**)&pWihl, g_Wihl);
    cudaGetSymbolAddress((void**)&pWhhh, g_Whhh);   cudaGetSymbolAddress((void**)&pWhhl, g_Whhl);
    cudaGetSymbolAddress((void**)&pWah,  g_Wah);    cudaGetSymbolAddress((void**)&pWal,  g_Wal);
    cudaGetSymbolAddress((void**)&pWouth, g_Wouth); cudaGetSymbolAddress((void**)&pWoutl, g_Woutl);
    cudaGetSymbolAddress((void**)&pxh,  g_xh);      cudaGetSymbolAddress((void**)&pxl,  g_xl);
    cudaGetSymbolAddress((void**)&phbh, g_hbh);     cudaGetSymbolAddress((void**)&phbl, g_hbl);
    cudaGetSymbolAddress((void**)&pvch, g_vch);     cudaGetSymbolAddress((void**)&pvcl, g_vcl);
    cudaGetSymbolAddress((void**)&p_a0, g_a0);
    cudaGetSymbolAddress((void**)&p_h,  g_h);

    // launch 0: all weight conversion
    convert_all<<<NB_CONV, 256>>>(W_ih, W_hh, W_a, W_out);
    // launch 1: a0 + x0
    build_init<<<(BB * 192 + BB * EE + 255) / 256, 256>>>(latent, style, style_emb, emb);
    // launch 2: h init (+ split)
    gemm_init<<<HH / 128, 128>>>(p_a0, 192, W_l2h, b_l2h, p_h, HH, 192);

    // decode loop: launches 3.. ; ncu (-s 5) captures gemm_q of step 0
    for (int t = 0; t < STEPS; t++) {
        gemm_gigh<<<96, 256, SMEM_128>>>(pxh, pxl, pWihh, pWihl,
                                         phbh, phbl, pWhhh, pWhhl);
        gru_gates<<<(BB * HH) / 256, 256>>>(b_ih, b_hh);
        gemm_q<<<32, 256, SMEM_128>>>(phbh, phbl, pWah, pWal);
        attn_kernel<<<BB, 256>>>(enc);
        gemm_logits<<<VV / 256, 256, SMEM_256>>>(pvch, pvcl, pWouth, pWoutl, b_out,
                                                 out + (size_t)t * VV, (long)STEPS * VV);
        if (t < STEPS - 1) argmax_embed<<<BB, 256>>>(out + (size_t)t * VV, emb);
    }
}

// round 9
// speedup vs baseline: 1.5264x; 1.5264x over previous
#include <cuda_runtime.h>
#include <cuda_bf16.h>
#include <math.h>

// Problem constants
#define BB 64
#define HH 1024
#define EE 512
#define VV 32000
#define TENC 64
#define STEPS 32
#define KOUT 2048   // 2*H

typedef unsigned long long ull;
typedef unsigned int u32;

// ---------------- scratch (device globals; no allocation allowed) ----------
__device__ float g_a0[BB * 192];
__device__ float g_h[BB * HH];            // fp32 master hidden state
__device__ float g_gip[2][BB * 3 * HH];   // split-K partials of x @ W_ih^T
__device__ float g_ghp[2][BB * 3 * HH];   // split-K partials of h @ W_hh^T
__device__ float g_qp[4][BB * HH];        // split-K partials of h @ W_a

// split-bf16 activations (16B-aligned for cp.async)
__device__ __align__(16) __nv_bfloat16 g_xh[BB * EE],  g_xl[BB * EE];
__device__ __align__(16) __nv_bfloat16 g_hbh[BB * HH], g_hbl[BB * HH];
__device__ __align__(16) __nv_bfloat16 g_vch[BB * KOUT], g_vcl[BB * KOUT];

// split-bf16 weights, all stored [N, K] row-major
__device__ __align__(16) __nv_bfloat16 g_Wihh[3 * HH * EE], g_Wihl[3 * HH * EE];
__device__ __align__(16) __nv_bfloat16 g_Whhh[3 * HH * HH], g_Whhl[3 * HH * HH];
__device__ __align__(16) __nv_bfloat16 g_Wah[HH * HH],      g_Wal[HH * HH];
__device__ __align__(16) __nv_bfloat16 g_Wouth[(size_t)VV * KOUT];
__device__ __align__(16) __nv_bfloat16 g_Woutl[(size_t)VV * KOUT];

// ====================== PTX helpers ========================================
__device__ __forceinline__ u32 smem_u32(const void* p) {
    u32 a;
    asm("{ .reg .u64 t; cvta.to.shared.u64 t, %1; cvt.u32.u64 %0, t; }"
        : "=r"(a) : "l"(p));
    return a;
}
__device__ __forceinline__ void cp16(u32 dst, const void* src) {
    asm volatile("cp.async.cg.shared.global [%0], [%1], 16;"
                 :: "r"(dst), "l"(src) : "memory");
}
__device__ __forceinline__ void cp_commit() {
    asm volatile("cp.async.commit_group;" ::: "memory");
}
__device__ __forceinline__ void cp_wait2() {
    asm volatile("cp.async.wait_group 2;" ::: "memory");
}
__device__ __forceinline__ void ldmx4(u32* r, u32 addr) {
    asm volatile("ldmatrix.sync.aligned.m8n8.x4.shared.b16 {%0,%1,%2,%3}, [%4];"
                 : "=r"(r[0]), "=r"(r[1]), "=r"(r[2]), "=r"(r[3]) : "r"(addr));
}
__device__ __forceinline__ void mma16816(float* c, const u32* a, const u32* b) {
    asm volatile(
        "mma.sync.aligned.m16n8k16.row.col.f32.bf16.bf16.f32 "
        "{%0,%1,%2,%3}, {%4,%5,%6,%7}, {%8,%9}, {%0,%1,%2,%3};"
        : "+f"(c[0]), "+f"(c[1]), "+f"(c[2]), "+f"(c[3])
        : "r"(a[0]), "r"(a[1]), "r"(a[2]), "r"(a[3]), "r"(b[0]), "r"(b[1]));
}

// ===========================================================================
// Split-bf16 HMMA GEMM body (512 threads, 16 warps):
//   C[64, N] = (Ah+Al)[64,Klen] @ (Bh+Bl)[N,Klen]^T (+ bias)
//   = Ah·Bh + Al·Bh + Ah·Bl  (Al·Bl dropped, ~2^-16 relative)
// CTA tile 64 x 128; warp grid 2m x 8n; warp tile 32 x 16.
// K-chunks of 32, cp.async 3-stage pipeline. Klen%32==0.
// SMEM pitch 80B: 8-row ldmatrix phases hit all 32 banks exactly once.
// ===========================================================================
#define OFF_AL (64 * 80)
#define OFF_BH (128 * 80)
#define OFF_BL (OFF_BH + 128 * 80)
#define BUFSZ  (80 * 384)           // 30720
#define GM_SMEM (3 * BUFSZ)         // 92160

__device__ __forceinline__ void load_chunk(
    u32 sb, const __nv_bfloat16* Ah, const __nv_bfloat16* Al,
    const __nv_bfloat16* Bh, const __nv_bfloat16* Bl,
    int n0, int ldk, int k0, int tid)
{
    // A: 128 rows (Ah|Al) x 64B = 512 x 16B transfers, 1 per thread
    {
        int i = tid;
        int seg = i & 3, row = (i >> 2) & 63, hi = i >> 8;
        const __nv_bfloat16* src = (hi ? Al : Ah) + (size_t)row * ldk + k0 + seg * 8;
        cp16(sb + (hi ? OFF_AL : 0) + row * 80 + seg * 16, src);
    }
    // B: 256 rows (Bh|Bl) x 64B = 1024 x 16B transfers, 2 per thread
#pragma unroll
    for (int r = 0; r < 2; r++) {
        int i = tid + r * 512;
        int seg = i & 3, row = (i >> 2) & 127;
        int hi = (i >= 512);
        const __nv_bfloat16* src = (hi ? Bl : Bh) + (size_t)(n0 + row) * ldk + k0 + seg * 8;
        cp16(sb + (hi ? OFF_BL : OFF_BH) + row * 80 + seg * 16, src);
    }
}

__device__ __forceinline__ void gemm_body(
    const __nv_bfloat16* __restrict__ Ah, const __nv_bfloat16* __restrict__ Al,
    const __nv_bfloat16* __restrict__ Bh, const __nv_bfloat16* __restrict__ Bl,
    const float* __restrict__ bias, float* __restrict__ C,
    long ldc, int Klen, int ldk, int n_cta, char* smem)
{
    const u32 sb = smem_u32(smem);
    const int tid = threadIdx.x, wid = tid >> 5, lane = tid & 31;
    const int wm = (wid & 1) * 32;     // warp m offset: 0 or 32
    const int wn = (wid >> 1) * 16;    // warp n offset: 0..112

    float acc[2][2][4] = {};

    const int nk = Klen >> 5;
    load_chunk(sb,         Ah, Al, Bh, Bl, n_cta, ldk, 0,  tid); cp_commit();
    load_chunk(sb + BUFSZ, Ah, Al, Bh, Bl, n_cta, ldk, 32, tid); cp_commit();

    const int lrow = lane & 15;
    const int lkof = (lane >> 4) * 16;

    for (int i = 0; i < nk; i++) {
        if (i + 2 < nk)
            load_chunk(sb + ((i + 2) % 3) * BUFSZ, Ah, Al, Bh, Bl,
                       n_cta, ldk, (i + 2) * 32, tid);
        cp_commit();
        cp_wait2();
        __syncthreads();

        const u32 bb = sb + (i % 3) * BUFSZ;
#pragma unroll
        for (int ks = 0; ks < 2; ks++) {
            const u32 kb = ks * 32 + lkof;
            u32 ah[2][4], al[2][4], bh[4], bl[4];
            ldmx4(ah[0], bb + (wm + lrow) * 80 + kb);
            ldmx4(ah[1], bb + (wm + 16 + lrow) * 80 + kb);
            ldmx4(al[0], bb + OFF_AL + (wm + lrow) * 80 + kb);
            ldmx4(al[1], bb + OFF_AL + (wm + 16 + lrow) * 80 + kb);
            ldmx4(bh, bb + OFF_BH + (wn + lrow) * 80 + kb);
            ldmx4(bl, bb + OFF_BL + (wn + lrow) * 80 + kb);

            u32 b0h[2] = { bh[0], bh[2] };
            u32 b1h[2] = { bh[1], bh[3] };
            u32 b0l[2] = { bl[0], bl[2] };
            u32 b1l[2] = { bl[1], bl[3] };
#pragma unroll
            for (int mt = 0; mt < 2; mt++) {
                float* c0 = acc[mt][0];
                float* c1 = acc[mt][1];
                mma16816(c0, ah[mt], b0h);
                mma16816(c1, ah[mt], b1h);
                mma16816(c0, al[mt], b0h);
                mma16816(c1, al[mt], b1h);
                mma16816(c0, ah[mt], b0l);
                mma16816(c1, ah[mt], b1l);
            }
        }
        __syncthreads();
    }

    // Epilogue: frag (mt, t): rows wm+mt*16+{l/4, l/4+8}, cols wn+t*8+2*(l%4)
#pragma unroll
    for (int mt = 0; mt < 2; mt++) {
        int m = wm + mt * 16 + (lane >> 2);
#pragma unroll
        for (int t = 0; t < 2; t++) {
            int n = n_cta + wn + t * 8 + 2 * (lane & 3);
            float* a = acc[mt][t];
            float b0 = bias ? bias[n] : 0.f;
            float b1 = bias ? bias[n + 1] : 0.f;
            float2 v0 = { a[0] + b0, a[1] + b1 };
            float2 v1 = { a[2] + b0, a[3] + b1 };
            *reinterpret_cast<float2*>(C + (size_t)m * ldc + n) = v0;
            *reinterpret_cast<float2*>(C + (size_t)(m + 8) * ldc + n) = v1;
        }
    }
}

// logits GEMM: 250 CTAs, 2 CTAs/SM
__global__ __launch_bounds__(512, 2)
void gemm_logits(const __nv_bfloat16* __restrict__ Ah, const __nv_bfloat16* __restrict__ Al,
                 const __nv_bfloat16* __restrict__ Bh, const __nv_bfloat16* __restrict__ Bl,
                 const float* __restrict__ bias, float* __restrict__ C, long ldc)
{
    extern __shared__ char smem[];
    gemm_body(Ah, Al, Bh, Bl, bias, C, ldc, KOUT, KOUT, blockIdx.x * 128, smem);
}

// q-GEMM 4-way split-K: 32 CTAs; slice s covers k in [s*256, (s+1)*256)
__global__ __launch_bounds__(512, 2)
void gemm_q(const __nv_bfloat16* __restrict__ hbh, const __nv_bfloat16* __restrict__ hbl,
            const __nv_bfloat16* __restrict__ Wah, const __nv_bfloat16* __restrict__ Wal)
{
    extern __shared__ char smem[];
    int s = blockIdx.x >> 3, nt = blockIdx.x & 7;
    int k0 = s * 256;
    gemm_body(hbh + k0, hbl + k0, Wah + k0, Wal + k0, nullptr,
              g_qp[s], HH, 256, HH, nt * 128, smem);
}

// fused gi + gh, each 2-way split-K: 96 CTAs
__global__ __launch_bounds__(512, 2)
void gemm_gigh(const __nv_bfloat16* __restrict__ xh, const __nv_bfloat16* __restrict__ xl,
               const __nv_bfloat16* __restrict__ Wihh, const __nv_bfloat16* __restrict__ Wihl,
               const __nv_bfloat16* __restrict__ hbh, const __nv_bfloat16* __restrict__ hbl,
               const __nv_bfloat16* __restrict__ Whhh, const __nv_bfloat16* __restrict__ Whhl)
{
    extern __shared__ char smem[];
    int bid = blockIdx.x;
    if (bid < 48) {
        int s = bid / 24, nt = bid % 24;
        int k0 = s * 256;
        gemm_body(xh + k0, xl + k0, Wihh + k0, Wihl + k0, nullptr,
                  g_gip[s], 3 * HH, 256, EE, nt * 128, smem);
    } else {
        bid -= 48;
        int s = bid / 24, nt = bid % 24;
        int k0 = s * 512;
        gemm_body(hbh + k0, hbl + k0, Whhh + k0, Whhl + k0, nullptr,
                  g_ghp[s], 3 * HH, 512, HH, nt * 128, smem);
    }
}

// ===================== conversion (single fused kernel) ====================
__device__ __forceinline__ void split2(float v, __nv_bfloat16& h, __nv_bfloat16& l) {
    h = __float2bfloat16(v);
    l = __float2bfloat16(v - __bfloat162float(h));
}

__device__ __forceinline__ void esplit_blk(const float* src, __nv_bfloat16* dh,
                                           __nv_bfloat16* dl, int bi, int tid)
{
    int i = bi * 256 + tid;
    split2(src[i], dh[i], dl[i]);
}

// one 32x32 transpose tile: src [K,N] fp32 -> dh/dl [N,K] bf16
__device__ __forceinline__ void tsplit_blk(const float* src, __nv_bfloat16* dh,
                                           __nv_bfloat16* dl, int K, int N,
                                           int bx, int by, int tid)
{
    __shared__ float t[32][33];
    int k0 = by * 32, n0 = bx * 32;
    int tx = tid & 31, ty = tid >> 5;   // 32 x 8
#pragma unroll
    for (int i = ty; i < 32; i += 8)
        t[i][tx] = src[(size_t)(k0 + i) * N + n0 + tx];
    __syncthreads();
#pragma unroll
    for (int i = ty; i < 32; i += 8) {
        float v = t[tx][i];
        __nv_bfloat16 h, l; split2(v, h, l);
        dh[(size_t)(n0 + i) * K + k0 + tx] = h;
        dl[(size_t)(n0 + i) * K + k0 + tx] = l;
    }
}

#define NB_WIH  6144    // 3*HH*EE / 256
#define NB_WHH 12288    // 3*HH*HH / 256
#define NB_WA   1024    // (HH/32)*(HH/32)
#define NB_WOUT 64000   // (VV/32)*(KOUT/32)
#define NB_CONV (NB_WIH + NB_WHH + NB_WA + NB_WOUT)

__global__ __launch_bounds__(256)
void convert_all(const float* __restrict__ W_ih, const float* __restrict__ W_hh,
                 const float* __restrict__ W_a,  const float* __restrict__ W_out)
{
    int b = blockIdx.x, tid = threadIdx.x;
    if (b < NB_WIH) {
        esplit_blk(W_ih, g_Wihh, g_Wihl, b, tid);
    } else if (b < NB_WIH + NB_WHH) {
        esplit_blk(W_hh, g_Whhh, g_Whhl, b - NB_WIH, tid);
    } else if (b < NB_WIH + NB_WHH + NB_WA) {
        int bi = b - NB_WIH - NB_WHH;
        tsplit_blk(W_a, g_Wah, g_Wal, HH, HH, bi % 32, bi / 32, tid);
    } else {
        int bi = b - NB_WIH - NB_WHH - NB_WA;
        tsplit_blk(W_out, g_Wouth, g_Woutl, KOUT, VV, bi % (VV / 32), bi / (VV / 32), tid);
    }
}

// ======================= init kernels ======================================
__global__ void build_init(const float* __restrict__ latent,
                           const int* __restrict__ style,
                           const float* __restrict__ style_emb,
                           const float* __restrict__ emb)
{
    int idx = blockIdx.x * blockDim.x + threadIdx.x;
    if (idx < BB * 192) {
        int b = idx / 192, k = idx - b * 192;
        g_a0[idx] = (k < 128) ? latent[b * 128 + k]
                              : style_emb[style[b] * 64 + (k - 128)];
    } else {
        int i = idx - BB * 192;
        if (i < BB * EE) {
            float v = emb[EE /* BOS=1 row */ + (i & (EE - 1))];
            split2(v, g_xh[i], g_xl[i]);
        }
    }
}

// h = a0 @ W_l2h + b (fp32 FFMA; also emits split-bf16 h)
__global__ __launch_bounds__(128)
void gemm_init(const float* __restrict__ A, int lda,
               const float* __restrict__ Bm, const float* __restrict__ bias,
               float* __restrict__ C, int N, int K)
{
    __shared__ float As[16][68];
    __shared__ float Bs[16][132];
    const int tid = threadIdx.x;
    const int n0 = blockIdx.x * 128;
    const int tm = (tid >> 4) << 3, tn = (tid & 15) << 3;
    float acc[8][8] = {};
    for (int k0 = 0; k0 < K; k0 += 16) {
        {
            int k = tid & 15, m = tid >> 4;
#pragma unroll
            for (int i = 0; i < 8; i++)
                As[k][m + i * 8] = A[(m + i * 8) * lda + k0 + k];
        }
        {
            int w = tid >> 5, n4 = (tid & 31) << 2;
#pragma unroll
            for (int kb = 0; kb < 4; kb++) {
                int k = kb * 4 + w;
                *reinterpret_cast<float4*>(&Bs[k][n4]) =
                    *reinterpret_cast<const float4*>(&Bm[(size_t)(k0 + k) * N + n0 + n4]);
            }
        }
        __syncthreads();
#pragma unroll
        for (int kk = 0; kk < 16; kk++) {
#pragma unroll
            for (int i = 0; i < 8; i++) {
                float a = As[kk][tm + i];
#pragma unroll
                for (int j = 0; j < 8; j++) acc[i][j] += a * Bs[kk][tn + j];
            }
        }
        __syncthreads();
    }
#pragma unroll
    for (int i = 0; i < 8; i++)
#pragma unroll
        for (int j = 0; j < 8; j++) {
            int n = n0 + tn + j;
            float v = acc[i][j] + (bias ? bias[n] : 0.f);
            int idx = (tm + i) * N + n;
            C[idx] = v;
            split2(v, g_hbh[idx], g_hbl[idx]);
        }
}

// ========================= per-step small kernels ==========================
__global__ void gru_gates(const float* __restrict__ b_ih, const float* __restrict__ b_hh)
{
    int idx = blockIdx.x * blockDim.x + threadIdx.x;   // 64*1024
    int b = idx >> 10, j = idx & 1023;
    int base = b * 3 * HH + j;
    float ir = g_gip[0][base]          + g_gip[1][base]          + b_ih[j];
    float iz = g_gip[0][base + HH]     + g_gip[1][base + HH]     + b_ih[j + HH];
    float in = g_gip[0][base + 2 * HH] + g_gip[1][base + 2 * HH] + b_ih[j + 2 * HH];
    float hr = g_ghp[0][base]          + g_ghp[1][base]          + b_hh[j];
    float hz = g_ghp[0][base + HH]     + g_ghp[1][base + HH]     + b_hh[j + HH];
    float hn = g_ghp[0][base + 2 * HH] + g_ghp[1][base + 2 * HH] + b_hh[j + 2 * HH];
    float r = 1.f / (1.f + expf(-(ir + hr)));
    float z = 1.f / (1.f + expf(-(iz + hz)));
    float n = tanhf(in + r * hn);
    float hnew = (1.f - z) * n + z * g_h[idx];
    g_h[idx] = hnew;
    __nv_bfloat16 hh, hl; split2(hnew, hh, hl);
    g_hbh[idx] = hh; g_hbl[idx] = hl;
    g_vch[b * KOUT + j] = hh; g_vcl[b * KOUT + j] = hl;
}

__global__ void attn_kernel(const float* __restrict__ enc)
{
    int b = blockIdx.x;
    int tid = threadIdx.x;              // 256
    __shared__ float s_q[HH];
    __shared__ float s_scores[TENC];
    __shared__ float s_attn[TENC];

    for (int i = tid; i < HH; i += 256) {
        int o = b * HH + i;
        s_q[i] = g_qp[0][o] + g_qp[1][o] + g_qp[2][o] + g_qp[3][o];
    }
    __syncthreads();

    int warp = tid >> 5, lane = tid & 31;
    for (int t = warp; t < TENC; t += 8) {
        const float* e = enc + ((size_t)b * TENC + t) * HH;
        float s = 0.f;
        for (int h = lane; h < HH; h += 32) s += s_q[h] * e[h];
#pragma unroll
        for (int o = 16; o; o >>= 1) s += __shfl_xor_sync(0xFFFFFFFFu, s, o);
        if (lane == 0) s_scores[t] = s;
    }
    __syncthreads();

    float mx = -1e30f;
    for (int t = 0; t < TENC; t++) mx = fmaxf(mx, s_scores[t]);
    if (tid < TENC) s_attn[tid] = expf(s_scores[tid] - mx);
    __syncthreads();
    float ssum = 0.f;
    for (int t = 0; t < TENC; t++) ssum += s_attn[t];
    float inv = 1.f / ssum;

    for (int h = tid; h < HH; h += 256) {
        float c = 0.f;
        const float* eb = enc + (size_t)b * TENC * HH + h;
#pragma unroll 8
        for (int t = 0; t < TENC; t++) c += s_attn[t] * eb[(size_t)t * HH];
        c *= inv;
        __nv_bfloat16 ch, cl; split2(c, ch, cl);
        g_vch[b * KOUT + HH + h] = ch;
        g_vcl[b * KOUT + HH + h] = cl;
    }
}

__global__ void argmax_embed(const float* __restrict__ logits_t,
                             const float* __restrict__ emb)
{
    int b = blockIdx.x;
    int tid = threadIdx.x;              // 256
    const float* L = logits_t + (size_t)b * STEPS * VV;

    float best = -1e30f; int bi = VV;
    for (int n = tid; n < VV; n += 256) {
        float v = L[n];
        if (v > best) { best = v; bi = n; }
    }
    __shared__ float sv[256]; __shared__ int si[256];
    sv[tid] = best; si[tid] = bi;
    __syncthreads();
    for (int s = 128; s; s >>= 1) {
        if (tid < s) {
            if (sv[tid + s] > sv[tid] ||
                (sv[tid + s] == sv[tid] && si[tid + s] < si[tid])) {
                sv[tid] = sv[tid + s]; si[tid] = si[tid + s];
            }
        }
        __syncthreads();
    }
    int tok = si[0];
    for (int e = tid; e < EE; e += 256) {
        float v = emb[(size_t)tok * EE + e];
        split2(v, g_xh[b * EE + e], g_xl[b * EE + e]);
    }
}

// ===========================================================================
extern "C" void kernel_launch(void* const* d_in, const int* in_sizes, int n_in,
                              void* d_out, int out_size)
{
    const float* latent    = (const float*)d_in[0];
    const int*   style     = (const int*)  d_in[1];
    const float* enc       = (const float*)d_in[2];
    const float* emb       = (const float*)d_in[4];
    const float* style_emb = (const float*)d_in[5];
    const float* W_l2h     = (const float*)d_in[6];
    const float* b_l2h     = (const float*)d_in[7];
    const float* W_ih      = (const float*)d_in[8];
    const float* W_hh      = (const float*)d_in[9];
    const float* b_ih      = (const float*)d_in[10];
    const float* b_hh      = (const float*)d_in[11];
    const float* W_a       = (const float*)d_in[12];
    const float* W_out     = (const float*)d_in[13];
    const float* b_out     = (const float*)d_in[14];
    float* out = (float*)d_out;

    cudaFuncSetAttribute(gemm_logits, cudaFuncAttributeMaxDynamicSharedMemorySize, GM_SMEM);
    cudaFuncSetAttribute(gemm_q,      cudaFuncAttributeMaxDynamicSharedMemorySize, GM_SMEM);
    cudaFuncSetAttribute(gemm_gigh,   cudaFuncAttributeMaxDynamicSharedMemorySize, GM_SMEM);

    __nv_bfloat16 *pWihh, *pWihl, *pWhhh, *pWhhl, *pWah, *pWal, *pWouth, *pWoutl;
    __nv_bfloat16 *pxh, *pxl, *phbh, *phbl, *pvch, *pvcl;
    float *p_a0, *p_h;
    cudaGetSymbolAddress((void**)&pWihh, g_Wihh);   cudaGetSymbolAddress((void**)&pWihl, g_Wihl);
    cudaGetSymbolAddress((void**)&pWhhh, g_Whhh);   cudaGetSymbolAddress((void**)&pWhhl, g_Whhl);
    cudaGetSymbolAddress((void**)&pWah,  g_Wah);    cudaGetSymbolAddress((void**)&pWal,  g_Wal);
    cudaGetSymbolAddress((void**)&pWouth, g_Wouth); cudaGetSymbolAddress((void**)&pWoutl, g_Woutl);
    cudaGetSymbolAddress((void**)&pxh,  g_xh);      cudaGetSymbolAddress((void**)&pxl,  g_xl);
    cudaGetSymbolAddress((void**)&phbh, g_hbh);     cudaGetSymbolAddress((void**)&phbl, g_hbl);
    cudaGetSymbolAddress((void**)&pvch, g_vch);     cudaGetSymbolAddress((void**)&pvcl, g_vcl);
    cudaGetSymbolAddress((void**)&p_a0, g_a0);
    cudaGetSymbolAddress((void**)&p_h,  g_h);

    // launch 0: all weight conversion
    convert_all<<<NB_CONV, 256>>>(W_ih, W_hh, W_a, W_out);
    // launch 1: a0 + x0
    build_init<<<(BB * 192 + BB * EE + 255) / 256, 256>>>(latent, style, style_emb, emb);
    // launch 2: h init (+ split)
    gemm_init<<<HH / 128, 128>>>(p_a0, 192, W_l2h, b_l2h, p_h, HH, 192);

    // decode loop
    for (int t = 0; t < STEPS; t++) {
        gemm_gigh<<<96, 512, GM_SMEM>>>(pxh, pxl, pWihh, pWihl,
                                        phbh, phbl, pWhhh, pWhhl);
        gru_gates<<<(BB * HH) / 256, 256>>>(b_ih, b_hh);
        gemm_q<<<32, 512, GM_SMEM>>>(phbh, phbl, pWah, pWal);
        attn_kernel<<<BB, 256>>>(enc);
        gemm_logits<<<VV / 128, 512, GM_SMEM>>>(pvch, pvcl, pWouth, pWoutl, b_out,
                                                out + (size_t)t * VV, (long)STEPS * VV);
        if (t < STEPS - 1) argmax_embed<<<BB, 256>>>(out + (size_t)t * VV, emb);
    }
}

// round 10
// speedup vs baseline: 1.6709x; 1.0947x over previous
#include <cuda_runtime.h>
#include <cuda_bf16.h>
#include <math.h>

// Problem constants
#define BB 64
#define HH 1024
#define EE 512
#define VV 32000
#define TENC 64
#define STEPS 32
#define KOUT 2048   // 2*H

typedef unsigned long long ull;
typedef unsigned int u32;

// ---------------- scratch (device globals; no allocation allowed) ----------
__device__ float g_a0[BB * 192];
__device__ float g_h[BB * HH];            // fp32 master hidden state
__device__ float g_gip[4][BB * 3 * HH];   // split-K partials of x @ W_ih^T
__device__ float g_ghp[4][BB * 3 * HH];   // split-K partials of h @ W_hh^T
__device__ float g_qp[8][BB * HH];        // split-K partials of h @ W_a

// split-bf16 activations (16B-aligned for cp.async)
__device__ __align__(16) __nv_bfloat16 g_xh[BB * EE],  g_xl[BB * EE];
__device__ __align__(16) __nv_bfloat16 g_hbh[BB * HH], g_hbl[BB * HH];
__device__ __align__(16) __nv_bfloat16 g_vch[BB * KOUT], g_vcl[BB * KOUT];

// split-bf16 weights, interleaved layout:
//   row n, K-chunk c (32 elems): [32 x hi bf16 | 32 x lo bf16] contiguous (128B)
//   row stride = 2*K elements
__device__ __align__(16) __nv_bfloat16 g_Wih[3 * HH * 2 * EE];
__device__ __align__(16) __nv_bfloat16 g_Whh[3 * HH * 2 * HH];
__device__ __align__(16) __nv_bfloat16 g_Wa[HH * 2 * HH];
__device__ __align__(16) __nv_bfloat16 g_Wout[(size_t)VV * 2 * KOUT];

// ====================== PTX helpers ========================================
__device__ __forceinline__ u32 smem_u32(const void* p) {
    u32 a;
    asm("{ .reg .u64 t; cvta.to.shared.u64 t, %1; cvt.u32.u64 %0, t; }"
        : "=r"(a) : "l"(p));
    return a;
}
__device__ __forceinline__ void cp16(u32 dst, const void* src) {
    asm volatile("cp.async.cg.shared.global [%0], [%1], 16;"
                 :: "r"(dst), "l"(src) : "memory");
}
__device__ __forceinline__ void cp_commit() {
    asm volatile("cp.async.commit_group;" ::: "memory");
}
__device__ __forceinline__ void cp_wait2() {
    asm volatile("cp.async.wait_group 2;" ::: "memory");
}
__device__ __forceinline__ void ldmx4(u32* r, u32 addr) {
    asm volatile("ldmatrix.sync.aligned.m8n8.x4.shared.b16 {%0,%1,%2,%3}, [%4];"
                 : "=r"(r[0]), "=r"(r[1]), "=r"(r[2]), "=r"(r[3]) : "r"(addr));
}
__device__ __forceinline__ void mma16816(float* c, const u32* a, const u32* b) {
    asm volatile(
        "mma.sync.aligned.m16n8k16.row.col.f32.bf16.bf16.f32 "
        "{%0,%1,%2,%3}, {%4,%5,%6,%7}, {%8,%9}, {%0,%1,%2,%3};"
        : "+f"(c[0]), "+f"(c[1]), "+f"(c[2]), "+f"(c[3])
        : "r"(a[0]), "r"(a[1]), "r"(a[2]), "r"(a[3]), "r"(b[0]), "r"(b[1]));
}

// ===========================================================================
// Split-bf16 HMMA GEMM body (512 threads, 16 warps):
//   C[64, N] = (Ah+Al)[64,Klen] @ (Bh+Bl)[N,Klen]^T (+ bias)
//   = Ah·Bh + Al·Bh + Ah·Bl  (Al·Bl dropped, ~2^-16 relative)
// A: separate h/l arrays, row stride ldkA (pointers pre-offset for split-K).
// B: interleaved array Bc, row stride ld2B, chunk index kc selects 128B block.
// CTA tile 64 x 128; warp grid 2m x 8n; warp tile 32 x 16.
// K-chunks of 32, cp.async 3-stage pipeline. Klen%32==0.
// ===========================================================================
#define OFF_AL (64 * 80)
#define OFF_BH (128 * 80)
#define OFF_BL (OFF_BH + 128 * 80)
#define BUFSZ  (80 * 384)           // 30720
#define GM_SMEM (3 * BUFSZ)         // 92160

__device__ __forceinline__ void load_chunk(
    u32 sb, const __nv_bfloat16* Ah, const __nv_bfloat16* Al,
    const __nv_bfloat16* Bc,
    int n0, int ldkA, size_t ld2B, int kc, int k0A, int tid)
{
    // A: 128 rows (Ah|Al) x 64B = 512 x 16B transfers, 1 per thread
    {
        int i = tid;
        int seg = i & 3, row = (i >> 2) & 63, hi = i >> 8;
        const __nv_bfloat16* src = (hi ? Al : Ah) + (size_t)row * ldkA + k0A + seg * 8;
        cp16(sb + (hi ? OFF_AL : 0) + row * 80 + seg * 16, src);
    }
    // B: 128 rows x 128B contiguous (64B hi + 64B lo) = 1024 x 16B, 2 per thread
#pragma unroll
    for (int r = 0; r < 2; r++) {
        int i = tid + r * 512;
        int seg8 = i & 7, row = i >> 3;   // row 0..127, seg8 0..7
        const __nv_bfloat16* src = Bc + (size_t)(n0 + row) * ld2B
                                      + (size_t)kc * 64 + seg8 * 8;
        cp16(sb + (seg8 < 4 ? OFF_BH : OFF_BL) + row * 80 + (seg8 & 3) * 16, src);
    }
}

__device__ __forceinline__ void gemm_body(
    const __nv_bfloat16* __restrict__ Ah, const __nv_bfloat16* __restrict__ Al,
    const __nv_bfloat16* __restrict__ Bc,
    const float* __restrict__ bias, float* __restrict__ C,
    long ldc, int Klen, int ldkA, size_t ld2B, int kcBase, int n_cta, char* smem)
{
    const u32 sb = smem_u32(smem);
    const int tid = threadIdx.x, wid = tid >> 5, lane = tid & 31;
    const int wm = (wid & 1) * 32;     // warp m offset: 0 or 32
    const int wn = (wid >> 1) * 16;    // warp n offset: 0..112

    float acc[2][2][4] = {};

    const int nk = Klen >> 5;
    load_chunk(sb,         Ah, Al, Bc, n_cta, ldkA, ld2B, kcBase,     0,  tid); cp_commit();
    load_chunk(sb + BUFSZ, Ah, Al, Bc, n_cta, ldkA, ld2B, kcBase + 1, 32, tid); cp_commit();

    const int lrow = lane & 15;
    const int lkof = (lane >> 4) * 16;

    for (int i = 0; i < nk; i++) {
        if (i + 2 < nk)
            load_chunk(sb + ((i + 2) % 3) * BUFSZ, Ah, Al, Bc,
                       n_cta, ldkA, ld2B, kcBase + i + 2, (i + 2) * 32, tid);
        cp_commit();
        cp_wait2();
        __syncthreads();

        const u32 bb = sb + (i % 3) * BUFSZ;
#pragma unroll
        for (int ks = 0; ks < 2; ks++) {
            const u32 kb = ks * 32 + lkof;
            u32 ah[2][4], al[2][4], bh[4], bl[4];
            ldmx4(ah[0], bb + (wm + lrow) * 80 + kb);
            ldmx4(ah[1], bb + (wm + 16 + lrow) * 80 + kb);
            ldmx4(al[0], bb + OFF_AL + (wm + lrow) * 80 + kb);
            ldmx4(al[1], bb + OFF_AL + (wm + 16 + lrow) * 80 + kb);
            ldmx4(bh, bb + OFF_BH + (wn + lrow) * 80 + kb);
            ldmx4(bl, bb + OFF_BL + (wn + lrow) * 80 + kb);

            u32 b0h[2] = { bh[0], bh[2] };
            u32 b1h[2] = { bh[1], bh[3] };
            u32 b0l[2] = { bl[0], bl[2] };
            u32 b1l[2] = { bl[1], bl[3] };
#pragma unroll
            for (int mt = 0; mt < 2; mt++) {
                float* c0 = acc[mt][0];
                float* c1 = acc[mt][1];
                mma16816(c0, ah[mt], b0h);
                mma16816(c1, ah[mt], b1h);
                mma16816(c0, al[mt], b0h);
                mma16816(c1, al[mt], b1h);
                mma16816(c0, ah[mt], b0l);
                mma16816(c1, ah[mt], b1l);
            }
        }
        __syncthreads();
    }

    // Epilogue: frag (mt, t): rows wm+mt*16+{l/4, l/4+8}, cols wn+t*8+2*(l%4)
#pragma unroll
    for (int mt = 0; mt < 2; mt++) {
        int m = wm + mt * 16 + (lane >> 2);
#pragma unroll
        for (int t = 0; t < 2; t++) {
            int n = n_cta + wn + t * 8 + 2 * (lane & 3);
            float* a = acc[mt][t];
            float b0 = bias ? bias[n] : 0.f;
            float b1 = bias ? bias[n + 1] : 0.f;
            float2 v0 = { a[0] + b0, a[1] + b1 };
            float2 v1 = { a[2] + b0, a[3] + b1 };
            *reinterpret_cast<float2*>(C + (size_t)m * ldc + n) = v0;
            *reinterpret_cast<float2*>(C + (size_t)(m + 8) * ldc + n) = v1;
        }
    }
}

// logits GEMM: 250 CTAs, 2 CTAs/SM
__global__ __launch_bounds__(512, 2)
void gemm_logits(const __nv_bfloat16* __restrict__ Ah, const __nv_bfloat16* __restrict__ Al,
                 const __nv_bfloat16* __restrict__ Bc,
                 const float* __restrict__ bias, float* __restrict__ C, long ldc)
{
    extern __shared__ char smem[];
    gemm_body(Ah, Al, Bc, bias, C, ldc, KOUT, KOUT, 2 * KOUT, 0,
              blockIdx.x * 128, smem);
}

// q-GEMM 8-way split-K: 64 CTAs; slice s covers k in [s*128, (s+1)*128)
__global__ __launch_bounds__(512, 2)
void gemm_q(const __nv_bfloat16* __restrict__ hbh, const __nv_bfloat16* __restrict__ hbl,
            const __nv_bfloat16* __restrict__ Wa)
{
    extern __shared__ char smem[];
    int s = blockIdx.x >> 3, nt = blockIdx.x & 7;
    int k0 = s * 128;
    gemm_body(hbh + k0, hbl + k0, Wa, nullptr, g_qp[s], HH,
              128, HH, 2 * HH, s * 4, nt * 128, smem);
}

// fused gi + gh, each 4-way split-K: 192 CTAs
__global__ __launch_bounds__(512, 2)
void gemm_gigh(const __nv_bfloat16* __restrict__ xh, const __nv_bfloat16* __restrict__ xl,
               const __nv_bfloat16* __restrict__ Wih,
               const __nv_bfloat16* __restrict__ hbh, const __nv_bfloat16* __restrict__ hbl,
               const __nv_bfloat16* __restrict__ Whh)
{
    extern __shared__ char smem[];
    int bid = blockIdx.x;
    if (bid < 96) {
        int s = bid / 24, nt = bid % 24;   // gi: K=512, slices of 128
        int k0 = s * 128;
        gemm_body(xh + k0, xl + k0, Wih, nullptr, g_gip[s], 3 * HH,
                  128, EE, 2 * EE, s * 4, nt * 128, smem);
    } else {
        bid -= 96;
        int s = bid / 24, nt = bid % 24;   // gh: K=1024, slices of 256
        int k0 = s * 256;
        gemm_body(hbh + k0, hbl + k0, Whh, nullptr, g_ghp[s], 3 * HH,
                  256, HH, 2 * HH, s * 8, nt * 128, smem);
    }
}

// ===================== conversion (single fused kernel) ====================
__device__ __forceinline__ void split2(float v, __nv_bfloat16& h, __nv_bfloat16& l) {
    h = __float2bfloat16(v);
    l = __float2bfloat16(v - __bfloat162float(h));
}

// elementwise split into interleaved layout; src already [N,K]
__device__ __forceinline__ void esplit_blk(const float* src, __nv_bfloat16* dc,
                                           int K, int bi, int tid)
{
    int i = bi * 256 + tid;
    int n = i / K, k = i % K;
    __nv_bfloat16 h, l; split2(src[i], h, l);
    size_t d = (size_t)n * 2 * K + ((k >> 5) << 6) + (k & 31);
    dc[d] = h; dc[d + 32] = l;
}

// transpose+split 32x32 tile: src [K,N] fp32 -> interleaved [N, 2K] bf16
__device__ __forceinline__ void tsplit_blk(const float* src, __nv_bfloat16* dc,
                                           int K, int N, int bx, int by, int tid)
{
    __shared__ float t[32][33];
    int k0 = by * 32, n0 = bx * 32;
    int tx = tid & 31, ty = tid >> 5;   // 32 x 8
#pragma unroll
    for (int i = ty; i < 32; i += 8)
        t[i][tx] = src[(size_t)(k0 + i) * N + n0 + tx];
    __syncthreads();
    size_t coff = (size_t)((k0 >> 5) << 6);
#pragma unroll
    for (int i = ty; i < 32; i += 8) {
        __nv_bfloat16 h, l; split2(t[tx][i], h, l);
        size_t d = (size_t)(n0 + i) * 2 * K + coff + tx;
        dc[d] = h; dc[d + 32] = l;
    }
}

#define NB_WIH  6144    // 3*HH*EE / 256
#define NB_WHH 12288    // 3*HH*HH / 256
#define NB_WA   1024    // (HH/32)*(HH/32)
#define NB_WOUT 64000   // (VV/32)*(KOUT/32)
#define NB_CONV (NB_WIH + NB_WHH + NB_WA + NB_WOUT)

__global__ __launch_bounds__(256)
void convert_all(const float* __restrict__ W_ih, const float* __restrict__ W_hh,
                 const float* __restrict__ W_a,  const float* __restrict__ W_out)
{
    int b = blockIdx.x, tid = threadIdx.x;
    if (b < NB_WIH) {
        esplit_blk(W_ih, g_Wih, EE, b, tid);
    } else if (b < NB_WIH + NB_WHH) {
        esplit_blk(W_hh, g_Whh, HH, b - NB_WIH, tid);
    } else if (b < NB_WIH + NB_WHH + NB_WA) {
        int bi = b - NB_WIH - NB_WHH;
        tsplit_blk(W_a, g_Wa, HH, HH, bi % 32, bi / 32, tid);
    } else {
        int bi = b - NB_WIH - NB_WHH - NB_WA;
        tsplit_blk(W_out, g_Wout, KOUT, VV, bi % (VV / 32), bi / (VV / 32), tid);
    }
}

// ======================= init kernels ======================================
__global__ void build_init(const float* __restrict__ latent,
                           const int* __restrict__ style,
                           const float* __restrict__ style_emb,
                           const float* __restrict__ emb)
{
    int idx = blockIdx.x * blockDim.x + threadIdx.x;
    if (idx < BB * 192) {
        int b = idx / 192, k = idx - b * 192;
        g_a0[idx] = (k < 128) ? latent[b * 128 + k]
                              : style_emb[style[b] * 64 + (k - 128)];
    } else {
        int i = idx - BB * 192;
        if (i < BB * EE) {
            float v = emb[EE /* BOS=1 row */ + (i & (EE - 1))];
            split2(v, g_xh[i], g_xl[i]);
        }
    }
}

// h = a0 @ W_l2h + b (fp32 FFMA; also emits split-bf16 h)
__global__ __launch_bounds__(128)
void gemm_init(const float* __restrict__ A, int lda,
               const float* __restrict__ Bm, const float* __restrict__ bias,
               float* __restrict__ C, int N, int K)
{
    __shared__ float As[16][68];
    __shared__ float Bs[16][132];
    const int tid = threadIdx.x;
    const int n0 = blockIdx.x * 128;
    const int tm = (tid >> 4) << 3, tn = (tid & 15) << 3;
    float acc[8][8] = {};
    for (int k0 = 0; k0 < K; k0 += 16) {
        {
            int k = tid & 15, m = tid >> 4;
#pragma unroll
            for (int i = 0; i < 8; i++)
                As[k][m + i * 8] = A[(m + i * 8) * lda + k0 + k];
        }
        {
            int w = tid >> 5, n4 = (tid & 31) << 2;
#pragma unroll
            for (int kb = 0; kb < 4; kb++) {
                int k = kb * 4 + w;
                *reinterpret_cast<float4*>(&Bs[k][n4]) =
                    *reinterpret_cast<const float4*>(&Bm[(size_t)(k0 + k) * N + n0 + n4]);
            }
        }
        __syncthreads();
#pragma unroll
        for (int kk = 0; kk < 16; kk++) {
#pragma unroll
            for (int i = 0; i < 8; i++) {
                float a = As[kk][tm + i];
#pragma unroll
                for (int j = 0; j < 8; j++) acc[i][j] += a * Bs[kk][tn + j];
            }
        }
        __syncthreads();
    }
#pragma unroll
    for (int i = 0; i < 8; i++)
#pragma unroll
        for (int j = 0; j < 8; j++) {
            int n = n0 + tn + j;
            float v = acc[i][j] + (bias ? bias[n] : 0.f);
            int idx = (tm + i) * N + n;
            C[idx] = v;
            split2(v, g_hbh[idx], g_hbl[idx]);
        }
}

// ========================= per-step small kernels ==========================
__global__ void gru_gates(const float* __restrict__ b_ih, const float* __restrict__ b_hh)
{
    int idx = blockIdx.x * blockDim.x + threadIdx.x;   // 64*1024
    int b = idx >> 10, j = idx & 1023;
    int base = b * 3 * HH + j;
    float ir = b_ih[j],          iz = b_ih[j + HH],      in = b_ih[j + 2 * HH];
    float hr = b_hh[j],          hz = b_hh[j + HH],      hn = b_hh[j + 2 * HH];
#pragma unroll
    for (int s = 0; s < 4; s++) {
        ir += g_gip[s][base];
        iz += g_gip[s][base + HH];
        in += g_gip[s][base + 2 * HH];
        hr += g_ghp[s][base];
        hz += g_ghp[s][base + HH];
        hn += g_ghp[s][base + 2 * HH];
    }
    float r = 1.f / (1.f + expf(-(ir + hr)));
    float z = 1.f / (1.f + expf(-(iz + hz)));
    float n = tanhf(in + r * hn);
    float hnew = (1.f - z) * n + z * g_h[idx];
    g_h[idx] = hnew;
    __nv_bfloat16 hh, hl; split2(hnew, hh, hl);
    g_hbh[idx] = hh; g_hbl[idx] = hl;
    g_vch[b * KOUT + j] = hh; g_vcl[b * KOUT + j] = hl;
}

__global__ __launch_bounds__(512)
void attn_kernel(const float* __restrict__ enc)
{
    int b = blockIdx.x;
    int tid = threadIdx.x;              // 512
    __shared__ float s_q[HH];
    __shared__ float s_scores[TENC];
    __shared__ float s_attn[TENC];

    for (int i = tid; i < HH; i += 512) {
        int o = b * HH + i;
        float q = 0.f;
#pragma unroll
        for (int s = 0; s < 8; s++) q += g_qp[s][o];
        s_q[i] = q;
    }
    __syncthreads();

    int warp = tid >> 5, lane = tid & 31;
    for (int t = warp; t < TENC; t += 16) {
        const float* e = enc + ((size_t)b * TENC + t) * HH;
        float s = 0.f;
        for (int h = lane; h < HH; h += 32) s += s_q[h] * e[h];
#pragma unroll
        for (int o = 16; o; o >>= 1) s += __shfl_xor_sync(0xFFFFFFFFu, s, o);
        if (lane == 0) s_scores[t] = s;
    }
    __syncthreads();

    float mx = -1e30f;
    for (int t = 0; t < TENC; t++) mx = fmaxf(mx, s_scores[t]);
    if (tid < TENC) s_attn[tid] = expf(s_scores[tid] - mx);
    __syncthreads();
    float ssum = 0.f;
    for (int t = 0; t < TENC; t++) ssum += s_attn[t];
    float inv = 1.f / ssum;

    for (int h = tid; h < HH; h += 512) {
        float c = 0.f;
        const float* eb = enc + (size_t)b * TENC * HH + h;
#pragma unroll 8
        for (int t = 0; t < TENC; t++) c += s_attn[t] * eb[(size_t)t * HH];
        c *= inv;
        __nv_bfloat16 ch, cl; split2(c, ch, cl);
        g_vch[b * KOUT + HH + h] = ch;
        g_vcl[b * KOUT + HH + h] = cl;
    }
}

__global__ __launch_bounds__(512)
void argmax_embed(const float* __restrict__ logits_t,
                  const float* __restrict__ emb)
{
    int b = blockIdx.x;
    int tid = threadIdx.x;              // 512
    const float* L = logits_t + (size_t)b * STEPS * VV;

    float best = -1e30f; int bi = VV;
    for (int n = tid; n < VV; n += 512) {
        float v = L[n];
        if (v > best) { best = v; bi = n; }
    }
    __shared__ float sv[512]; __shared__ int si[512];
    sv[tid] = best; si[tid] = bi;
    __syncthreads();
    for (int s = 256; s; s >>= 1) {
        if (tid < s) {
            if (sv[tid + s] > sv[tid] ||
                (sv[tid + s] == sv[tid] && si[tid + s] < si[tid])) {
                sv[tid] = sv[tid + s]; si[tid] = si[tid + s];
            }
        }
        __syncthreads();
    }
    int tok = si[0];
    for (int e = tid; e < EE; e += 512) {
        float v = emb[(size_t)tok * EE + e];
        split2(v, g_xh[b * EE + e], g_xl[b * EE + e]);
    }
}

// ===========================================================================
extern "C" void kernel_launch(void* const* d_in, const int* in_sizes, int n_in,
                              void* d_out, int out_size)
{
    const float* latent    = (const float*)d_in[0];
    const int*   style     = (const int*)  d_in[1];
    const float* enc       = (const float*)d_in[2];
    const float* emb       = (const float*)d_in[4];
    const float* style_emb = (const float*)d_in[5];
    const float* W_l2h     = (const float*)d_in[6];
    const float* b_l2h     = (const float*)d_in[7];
    const float* W_ih      = (const float*)d_in[8];
    const float* W_hh      = (const float*)d_in[9];
    const float* b_ih      = (const float*)d_in[10];
    const float* b_hh      = (const float*)d_in[11];
    const float* W_a       = (const float*)d_in[12];
    const float* W_out     = (const float*)d_in[13];
    const float* b_out     = (const float*)d_in[14];
    float* out = (float*)d_out;

    cudaFuncSetAttribute(gemm_logits, cudaFuncAttributeMaxDynamicSharedMemorySize, GM_SMEM);
    cudaFuncSetAttribute(gemm_q,      cudaFuncAttributeMaxDynamicSharedMemorySize, GM_SMEM);
    cudaFuncSetAttribute(gemm_gigh,   cudaFuncAttributeMaxDynamicSharedMemorySize, GM_SMEM);

    __nv_bfloat16 *pWih, *pWhh, *pWa, *pWout;
    __nv_bfloat16 *pxh, *pxl, *phbh, *phbl, *pvch, *pvcl;
    float *p_a0, *p_h;
    cudaGetSymbolAddress((void**)&pWih,  g_Wih);
    cudaGetSymbolAddress((void**)&pWhh,  g_Whh);
    cudaGetSymbolAddress((void**)&pWa,   g_Wa);
    cudaGetSymbolAddress((void**)&pWout, g_Wout);
    cudaGetSymbolAddress((void**)&pxh,  g_xh);      cudaGetSymbolAddress((void**)&pxl,  g_xl);
    cudaGetSymbolAddress((void**)&phbh, g_hbh);     cudaGetSymbolAddress((void**)&phbl, g_hbl);
    cudaGetSymbolAddress((void**)&pvch, g_vch);     cudaGetSymbolAddress((void**)&pvcl, g_vcl);
    cudaGetSymbolAddress((void**)&p_a0, g_a0);
    cudaGetSymbolAddress((void**)&p_h,  g_h);

    // launch 0: all weight conversion (interleaved layout)
    convert_all<<<NB_CONV, 256>>>(W_ih, W_hh, W_a, W_out);
    // launch 1: a0 + x0
    build_init<<<(BB * 192 + BB * EE + 255) / 256, 256>>>(latent, style, style_emb, emb);
    // launch 2: h init (+ split)
    gemm_init<<<HH / 128, 128>>>(p_a0, 192, W_l2h, b_l2h, p_h, HH, 192);

    // decode loop
    for (int t = 0; t < STEPS; t++) {
        gemm_gigh<<<192, 512, GM_SMEM>>>(pxh, pxl, pWih, phbh, phbl, pWhh);
        gru_gates<<<(BB * HH) / 256, 256>>>(b_ih, b_hh);
        gemm_q<<<64, 512, GM_SMEM>>>(phbh, phbl, pWa);
        attn_kernel<<<BB, 512>>>(enc);
        gemm_logits<<<VV / 128, 512, GM_SMEM>>>(pvch, pvcl, pWout, b_out,
                                                out + (size_t)t * VV, (long)STEPS * VV);
        if (t < STEPS - 1) argmax_embed<<<BB, 512>>>(out + (size_t)t * VV, emb);
    }
}

// round 11
// speedup vs baseline: 2.0183x; 1.2079x over previous
#include <cuda_runtime.h>
#include <cuda_bf16.h>
#include <math.h>

// Problem constants
#define BB 64
#define HH 1024
#define EE 512
#define VV 32000
#define TENC 64
#define STEPS 32
#define KOUT 2048   // 2*H

typedef unsigned long long ull;
typedef unsigned int u32;

// ---------------- scratch (device globals; no allocation allowed) ----------
__device__ float g_a0[BB * 192];
__device__ float g_h[BB * HH];            // fp32 master hidden state
__device__ float g_gip[4][BB * 3 * HH];   // split-K partials of x @ W_ih^T
__device__ float g_ghp[4][BB * 3 * HH];   // split-K partials of h @ W_hh^T
__device__ float g_qp[8][BB * HH];        // split-K partials of h @ W_a

// Tiled+swizzled activations: [kchunk][64 rows x 128B(32hi|32lo)] = 8KB blocks
__device__ __align__(16) __nv_bfloat16 g_xt[BB * EE * 2];     // 16 chunks
__device__ __align__(16) __nv_bfloat16 g_ht[BB * HH * 2];     // 32 chunks
__device__ __align__(16) __nv_bfloat16 g_vt[BB * KOUT * 2];   // 64 chunks

// Tiled+swizzled weights: [ntile][kchunk][128 rows x 128B(32hi|32lo)] = 16KB blocks
__device__ __align__(16) __nv_bfloat16 g_Wih[3 * HH * 2 * EE];
__device__ __align__(16) __nv_bfloat16 g_Whh[3 * HH * 2 * HH];
__device__ __align__(16) __nv_bfloat16 g_Wa[HH * 2 * HH];
__device__ __align__(16) __nv_bfloat16 g_Wout[(size_t)VV * 2 * KOUT];

// ====================== PTX helpers ========================================
__device__ __forceinline__ u32 smem_u32(const void* p) {
    u32 a;
    asm("{ .reg .u64 t; cvta.to.shared.u64 t, %1; cvt.u32.u64 %0, t; }"
        : "=r"(a) : "l"(p));
    return a;
}
#define MBAR_INIT(a, c) \
    asm volatile("mbarrier.init.shared.b64 [%0], %1;" :: "r"(a), "r"(c) : "memory")
#define MBAR_EXPECT(a, b) \
    asm volatile("mbarrier.arrive.expect_tx.shared.b64 _, [%0], %1;" :: "r"(a), "r"(b) : "memory")
#define FENCE_ASYNC() \
    asm volatile("fence.proxy.async.shared::cta;" ::: "memory")
#define BULK_G2S(dst, src, sz, mb) \
    asm volatile("cp.async.bulk.shared::cluster.global.mbarrier::complete_tx::bytes " \
                 "[%0], [%1], %2, [%3];" \
                 :: "r"(dst), "l"(src), "r"(sz), "r"(mb) : "memory")

__device__ __forceinline__ void mbar_wait(u32 addr, u32 parity) {
    asm volatile(
        "{\n\t.reg .pred P;\n\t"
        "W%=:\n\t"
        "mbarrier.try_wait.parity.shared.b64 P, [%0], %1;\n\t"
        "@P bra D%=;\n\t"
        "bra W%=;\n\t"
        "D%=:\n\t}"
        :: "r"(addr), "r"(parity) : "memory");
}
__device__ __forceinline__ void ldmx4(u32* r, u32 addr) {
    asm volatile("ldmatrix.sync.aligned.m8n8.x4.shared.b16 {%0,%1,%2,%3}, [%4];"
                 : "=r"(r[0]), "=r"(r[1]), "=r"(r[2]), "=r"(r[3]) : "r"(addr));
}
__device__ __forceinline__ void mma16816(float* c, const u32* a, const u32* b) {
    asm volatile(
        "mma.sync.aligned.m16n8k16.row.col.f32.bf16.bf16.f32 "
        "{%0,%1,%2,%3}, {%4,%5,%6,%7}, {%8,%9}, {%0,%1,%2,%3};"
        : "+f"(c[0]), "+f"(c[1]), "+f"(c[2]), "+f"(c[3])
        : "r"(a[0]), "r"(a[1]), "r"(a[2]), "r"(a[3]), "r"(b[0]), "r"(b[1]));
}

// ===========================================================================
// Split-bf16 HMMA GEMM body (512 threads, 16 warps):
//   C[64, N] = (Ah+Al)[64,Klen] @ (Bh+Bl)[N,Klen]^T (+ bias)
//   = Ah·Bh + Al·Bh + Ah·Bl  (Al·Bl dropped, ~2^-16 relative)
// A/B pre-tiled + SW128-swizzled in GMEM; loaded via 2 cp.async.bulk per stage.
// CTA tile 64 x 128; warp grid 2m x 8n; warp tile 32 x 16.
// K-chunks of 32, 3-stage mbarrier pipeline. nk >= 3.
// ===========================================================================
#define ABLK 8192
#define BBLK 16384
#define STGSZ (ABLK + BBLK)          // 24576
#define GM_SMEM (3 * STGSZ + 64)     // stages + 3 mbarriers

__device__ __forceinline__ void gemm_body(
    const __nv_bfloat16* __restrict__ At, const __nv_bfloat16* __restrict__ Bt,
    const float* __restrict__ bias, float* __restrict__ C,
    long ldc, int nk, int nkTot, int kcBase, int ntile, char* smem)
{
    const u32 sb = smem_u32(smem);
    const u32 mb = sb + 3 * STGSZ;
    const int tid = threadIdx.x, wid = tid >> 5, lane = tid & 31;
    const int wm = (wid & 1) * 32;     // warp m offset: 0 or 32
    const int wn = (wid >> 1) * 16;    // warp n offset: 0..112
    const int n_cta = ntile * 128;

    if (tid == 0) {
        MBAR_INIT(mb, 1); MBAR_INIT(mb + 8, 1); MBAR_INIT(mb + 16, 1);
    }
    FENCE_ASYNC();
    __syncthreads();

    const char* Ab = (const char*)At + (size_t)kcBase * ABLK;
    const char* Bb = (const char*)Bt + ((size_t)ntile * nkTot + kcBase) * BBLK;

    if (tid == 0) {
#pragma unroll
        for (int j = 0; j < 3; j++) {
            u32 m = mb + 8 * j;
            MBAR_EXPECT(m, STGSZ);
            BULK_G2S(sb + j * STGSZ,        Ab + (size_t)j * ABLK, ABLK, m);
            BULK_G2S(sb + j * STGSZ + ABLK, Bb + (size_t)j * BBLK, BBLK, m);
        }
    }

    float acc[2][2][4] = {};

    const int lrow = lane & 15;
    const int lkof = (lane >> 4) * 16;
    // swizzled row bases: addr = rowbase + (colbyte ^ xm), xm = (row&7)<<4
    const int a0r = wm + lrow,  a1r = wm + 16 + lrow,  brr = wn + lrow;
    const u32 a0b = a0r * 128,  a0x = (a0r & 7) << 4;
    const u32 a1b = a1r * 128,  a1x = (a1r & 7) << 4;
    const u32 brb = brr * 128,  brx = (brr & 7) << 4;

    for (int j = 0; j < nk; j++) {
        const int s = j % 3;
        mbar_wait(mb + 8 * s, (j / 3) & 1);

        const u32 bbA = sb + s * STGSZ;
        const u32 bbB = bbA + ABLK;
#pragma unroll
        for (int ks = 0; ks < 2; ks++) {
            const u32 o = ks * 32 + lkof;
            u32 ah[2][4], al[2][4], bh[4], bl[4];
            ldmx4(ah[0], bbA + a0b + (o ^ a0x));
            ldmx4(ah[1], bbA + a1b + (o ^ a1x));
            ldmx4(al[0], bbA + a0b + ((o + 64) ^ a0x));
            ldmx4(al[1], bbA + a1b + ((o + 64) ^ a1x));
            ldmx4(bh,    bbB + brb + (o ^ brx));
            ldmx4(bl,    bbB + brb + ((o + 64) ^ brx));

            u32 b0h[2] = { bh[0], bh[2] };
            u32 b1h[2] = { bh[1], bh[3] };
            u32 b0l[2] = { bl[0], bl[2] };
            u32 b1l[2] = { bl[1], bl[3] };
#pragma unroll
            for (int mt = 0; mt < 2; mt++) {
                float* c0 = acc[mt][0];
                float* c1 = acc[mt][1];
                mma16816(c0, ah[mt], b0h);
                mma16816(c1, ah[mt], b1h);
                mma16816(c0, al[mt], b0h);
                mma16816(c1, al[mt], b1h);
                mma16816(c0, ah[mt], b0l);
                mma16816(c1, ah[mt], b1l);
            }
        }
        __syncthreads();   // all warps done reading stage s

        if (j + 3 < nk && tid == 0) {
            u32 m = mb + 8 * s;
            MBAR_EXPECT(m, STGSZ);
            BULK_G2S(sb + s * STGSZ,        Ab + (size_t)(j + 3) * ABLK, ABLK, m);
            BULK_G2S(sb + s * STGSZ + ABLK, Bb + (size_t)(j + 3) * BBLK, BBLK, m);
        }
    }

    // Epilogue: frag (mt, t): rows wm+mt*16+{l/4, l/4+8}, cols wn+t*8+2*(l%4)
#pragma unroll
    for (int mt = 0; mt < 2; mt++) {
        int m = wm + mt * 16 + (lane >> 2);
#pragma unroll
        for (int t = 0; t < 2; t++) {
            int n = n_cta + wn + t * 8 + 2 * (lane & 3);
            float* a = acc[mt][t];
            float b0 = bias ? bias[n] : 0.f;
            float b1 = bias ? bias[n + 1] : 0.f;
            float2 v0 = { a[0] + b0, a[1] + b1 };
            float2 v1 = { a[2] + b0, a[3] + b1 };
            *reinterpret_cast<float2*>(C + (size_t)m * ldc + n) = v0;
            *reinterpret_cast<float2*>(C + (size_t)(m + 8) * ldc + n) = v1;
        }
    }
}

// logits GEMM: 250 CTAs
__global__ __launch_bounds__(512, 2)
void gemm_logits(const __nv_bfloat16* __restrict__ At, const __nv_bfloat16* __restrict__ Bt,
                 const float* __restrict__ bias, float* __restrict__ C, long ldc)
{
    extern __shared__ char smem[];
    gemm_body(At, Bt, bias, C, ldc, KOUT / 32, KOUT / 32, 0, blockIdx.x, smem);
}

// q-GEMM 8-way split-K: 64 CTAs; slice s covers chunks [s*4, s*4+4)
__global__ __launch_bounds__(512, 2)
void gemm_q(const __nv_bfloat16* __restrict__ ht, const __nv_bfloat16* __restrict__ Wa)
{
    extern __shared__ char smem[];
    int s = blockIdx.x >> 3, nt = blockIdx.x & 7;
    gemm_body(ht, Wa, nullptr, g_qp[s], HH, 4, HH / 32, s * 4, nt, smem);
}

// fused gi + gh, each 4-way split-K: 192 CTAs
__global__ __launch_bounds__(512, 2)
void gemm_gigh(const __nv_bfloat16* __restrict__ xt, const __nv_bfloat16* __restrict__ Wih,
               const __nv_bfloat16* __restrict__ ht, const __nv_bfloat16* __restrict__ Whh)
{
    extern __shared__ char smem[];
    int bid = blockIdx.x;
    if (bid < 96) {
        int s = bid / 24, nt = bid % 24;   // gi: K=512 -> 4 slices x 4 chunks
        gemm_body(xt, Wih, nullptr, g_gip[s], 3 * HH, 4, EE / 32, s * 4, nt, smem);
    } else {
        bid -= 96;
        int s = bid / 24, nt = bid % 24;   // gh: K=1024 -> 4 slices x 8 chunks
        gemm_body(ht, Whh, nullptr, g_ghp[s], 3 * HH, 8, HH / 32, s * 8, nt, smem);
    }
}

// ===================== split + tiled-store helpers =========================
__device__ __forceinline__ void split2(float v, __nv_bfloat16& h, __nv_bfloat16& l) {
    h = __float2bfloat16(v);
    l = __float2bfloat16(v - __bfloat162float(h));
}

// store one activation element into tiled+swizzled layout (8KB A-blocks)
__device__ __forceinline__ void store_act(__nv_bfloat16* base, int kc, int r, int c, float v) {
    __nv_bfloat16 h, l; split2(v, h, l);
    u32 xm = (r & 7) << 4;
    char* p = (char*)base + (size_t)kc * ABLK + r * 128;
    *reinterpret_cast<__nv_bfloat16*>(p + ((c * 2) ^ xm)) = h;
    *reinterpret_cast<__nv_bfloat16*>(p + ((64 + c * 2) ^ xm)) = l;
}

// store one weight element into tiled+swizzled layout (16KB B-blocks)
__device__ __forceinline__ void store_w(__nv_bfloat16* base, int nkTot, int n, int k, float v) {
    __nv_bfloat16 h, l; split2(v, h, l);
    int nt = n >> 7, r = n & 127, kc = k >> 5, c = k & 31;
    u32 xm = (r & 7) << 4;
    char* p = (char*)base + ((size_t)nt * nkTot + kc) * BBLK + r * 128;
    *reinterpret_cast<__nv_bfloat16*>(p + ((c * 2) ^ xm)) = h;
    *reinterpret_cast<__nv_bfloat16*>(p + ((64 + c * 2) ^ xm)) = l;
}

// elementwise: src already [N,K]
__device__ __forceinline__ void esplit_blk(const float* src, __nv_bfloat16* dc,
                                           int K, int bi, int tid)
{
    int i = bi * 256 + tid;
    store_w(dc, K >> 5, i / K, i % K, src[i]);
}

// transpose 32x32 tile: src [K,N] fp32 -> tiled [N-major] layout
__device__ __forceinline__ void tsplit_blk(const float* src, __nv_bfloat16* dc,
                                           int K, int N, int bx, int by, int tid)
{
    __shared__ float t[32][33];
    int k0 = by * 32, n0 = bx * 32;
    int tx = tid & 31, ty = tid >> 5;   // 32 x 8
#pragma unroll
    for (int i = ty; i < 32; i += 8)
        t[i][tx] = src[(size_t)(k0 + i) * N + n0 + tx];
    __syncthreads();
#pragma unroll
    for (int i = ty; i < 32; i += 8)
        store_w(dc, K >> 5, n0 + i, k0 + tx, t[tx][i]);
}

#define NB_WIH  6144    // 3*HH*EE / 256
#define NB_WHH 12288    // 3*HH*HH / 256
#define NB_WA   1024    // (HH/32)*(HH/32)
#define NB_WOUT 64000   // (VV/32)*(KOUT/32)
#define NB_CONV (NB_WIH + NB_WHH + NB_WA + NB_WOUT)

__global__ __launch_bounds__(256)
void convert_all(const float* __restrict__ W_ih, const float* __restrict__ W_hh,
                 const float* __restrict__ W_a,  const float* __restrict__ W_out)
{
    int b = blockIdx.x, tid = threadIdx.x;
    if (b < NB_WIH) {
        esplit_blk(W_ih, g_Wih, EE, b, tid);
    } else if (b < NB_WIH + NB_WHH) {
        esplit_blk(W_hh, g_Whh, HH, b - NB_WIH, tid);
    } else if (b < NB_WIH + NB_WHH + NB_WA) {
        int bi = b - NB_WIH - NB_WHH;
        tsplit_blk(W_a, g_Wa, HH, HH, bi % 32, bi / 32, tid);
    } else {
        int bi = b - NB_WIH - NB_WHH - NB_WA;
        tsplit_blk(W_out, g_Wout, KOUT, VV, bi % (VV / 32), bi / (VV / 32), tid);
    }
}

// ======================= init kernels ======================================
__global__ void build_init(const float* __restrict__ latent,
                           const int* __restrict__ style,
                           const float* __restrict__ style_emb,
                           const float* __restrict__ emb)
{
    int idx = blockIdx.x * blockDim.x + threadIdx.x;
    if (idx < BB * 192) {
        int b = idx / 192, k = idx - b * 192;
        g_a0[idx] = (k < 128) ? latent[b * 128 + k]
                              : style_emb[style[b] * 64 + (k - 128)];
    } else {
        int i = idx - BB * 192;
        if (i < BB * EE) {
            int b = i >> 9, e = i & (EE - 1);
            float v = emb[EE /* BOS=1 row */ + e];
            store_act(g_xt, e >> 5, b, e & 31, v);
        }
    }
}

// h = a0 @ W_l2h + b (fp32 FFMA; also emits tiled split-bf16 h)
__global__ __launch_bounds__(128)
void gemm_init(const float* __restrict__ A, int lda,
               const float* __restrict__ Bm, const float* __restrict__ bias,
               float* __restrict__ C, int N, int K)
{
    __shared__ float As[16][68];
    __shared__ float Bs[16][132];
    const int tid = threadIdx.x;
    const int n0 = blockIdx.x * 128;
    const int tm = (tid >> 4) << 3, tn = (tid & 15) << 3;
    float acc[8][8] = {};
    for (int k0 = 0; k0 < K; k0 += 16) {
        {
            int k = tid & 15, m = tid >> 4;
#pragma unroll
            for (int i = 0; i < 8; i++)
                As[k][m + i * 8] = A[(m + i * 8) * lda + k0 + k];
        }
        {
            int w = tid >> 5, n4 = (tid & 31) << 2;
#pragma unroll
            for (int kb = 0; kb < 4; kb++) {
                int k = kb * 4 + w;
                *reinterpret_cast<float4*>(&Bs[k][n4]) =
                    *reinterpret_cast<const float4*>(&Bm[(size_t)(k0 + k) * N + n0 + n4]);
            }
        }
        __syncthreads();
#pragma unroll
        for (int kk = 0; kk < 16; kk++) {
#pragma unroll
            for (int i = 0; i < 8; i++) {
                float a = As[kk][tm + i];
#pragma unroll
                for (int j = 0; j < 8; j++) acc[i][j] += a * Bs[kk][tn + j];
            }
        }
        __syncthreads();
    }
#pragma unroll
    for (int i = 0; i < 8; i++)
#pragma unroll
        for (int j = 0; j < 8; j++) {
            int n = n0 + tn + j;
            float v = acc[i][j] + (bias ? bias[n] : 0.f);
            int m = tm + i;
            C[(size_t)m * N + n] = v;
            store_act(g_ht, n >> 5, m, n & 31, v);
        }
}

// ========================= per-step small kernels ==========================
__global__ void gru_gates(const float* __restrict__ b_ih, const float* __restrict__ b_hh)
{
    int idx = blockIdx.x * blockDim.x + threadIdx.x;   // 64*1024
    int b = idx >> 10, j = idx & 1023;
    int base = b * 3 * HH + j;
    float ir = b_ih[j], iz = b_ih[j + HH], in = b_ih[j + 2 * HH];
    float hr = b_hh[j], hz = b_hh[j + HH], hn = b_hh[j + 2 * HH];
#pragma unroll
    for (int s = 0; s < 4; s++) {
        ir += g_gip[s][base];
        iz += g_gip[s][base + HH];
        in += g_gip[s][base + 2 * HH];
        hr += g_ghp[s][base];
        hz += g_ghp[s][base + HH];
        hn += g_ghp[s][base + 2 * HH];
    }
    float r = 1.f / (1.f + expf(-(ir + hr)));
    float z = 1.f / (1.f + expf(-(iz + hz)));
    float n = tanhf(in + r * hn);
    float hnew = (1.f - z) * n + z * g_h[idx];
    g_h[idx] = hnew;
    int kc = j >> 5, c = j & 31;
    store_act(g_ht, kc, b, c, hnew);
    store_act(g_vt, kc, b, c, hnew);   // vcat chunks 0..31 = h
}

__global__ __launch_bounds__(512)
void attn_kernel(const float* __restrict__ enc)
{
    int b = blockIdx.x;
    int tid = threadIdx.x;              // 512
    __shared__ float s_q[HH];
    __shared__ float s_scores[TENC];
    __shared__ float s_attn[TENC];

    for (int i = tid; i < HH; i += 512) {
        int o = b * HH + i;
        float q = 0.f;
#pragma unroll
        for (int s = 0; s < 8; s++) q += g_qp[s][o];
        s_q[i] = q;
    }
    __syncthreads();

    int warp = tid >> 5, lane = tid & 31;
    for (int t = warp; t < TENC; t += 16) {
        const float* e = enc + ((size_t)b * TENC + t) * HH;
        float s = 0.f;
        for (int h = lane; h < HH; h += 32) s += s_q[h] * e[h];
#pragma unroll
        for (int o = 16; o; o >>= 1) s += __shfl_xor_sync(0xFFFFFFFFu, s, o);
        if (lane == 0) s_scores[t] = s;
    }
    __syncthreads();

    float mx = -1e30f;
    for (int t = 0; t < TENC; t++) mx = fmaxf(mx, s_scores[t]);
    if (tid < TENC) s_attn[tid] = expf(s_scores[tid] - mx);
    __syncthreads();
    float ssum = 0.f;
    for (int t = 0; t < TENC; t++) ssum += s_attn[t];
    float inv = 1.f / ssum;

    for (int h = tid; h < HH; h += 512) {
        float c = 0.f;
        const float* eb = enc + (size_t)b * TENC * HH + h;
#pragma unroll 8
        for (int t = 0; t < TENC; t++) c += s_attn[t] * eb[(size_t)t * HH];
        c *= inv;
        store_act(g_vt, 32 + (h >> 5), b, h & 31, c);   // vcat chunks 32..63 = ctx
    }
}

__global__ __launch_bounds__(512)
void argmax_embed(const float* __restrict__ logits_t,
                  const float* __restrict__ emb)
{
    int b = blockIdx.x;
    int tid = threadIdx.x;              // 512
    const float* L = logits_t + (size_t)b * STEPS * VV;

    float best = -1e30f; int bi = VV;
    for (int n = tid; n < VV; n += 512) {
        float v = L[n];
        if (v > best) { best = v; bi = n; }
    }
    __shared__ float sv[512]; __shared__ int si[512];
    sv[tid] = best; si[tid] = bi;
    __syncthreads();
    for (int s = 256; s; s >>= 1) {
        if (tid < s) {
            if (sv[tid + s] > sv[tid] ||
                (sv[tid + s] == sv[tid] && si[tid + s] < si[tid])) {
                sv[tid] = sv[tid + s]; si[tid] = si[tid + s];
            }
        }
        __syncthreads();
    }
    int tok = si[0];
    for (int e = tid; e < EE; e += 512) {
        float v = emb[(size_t)tok * EE + e];
        store_act(g_xt, e >> 5, b, e & 31, v);
    }
}

// ===========================================================================
extern "C" void kernel_launch(void* const* d_in, const int* in_sizes, int n_in,
                              void* d_out, int out_size)
{
    const float* latent    = (const float*)d_in[0];
    const int*   style     = (const int*)  d_in[1];
    const float* enc       = (const float*)d_in[2];
    const float* emb       = (const float*)d_in[4];
    const float* style_emb = (const float*)d_in[5];
    const float* W_l2h     = (const float*)d_in[6];
    const float* b_l2h     = (const float*)d_in[7];
    const float* W_ih      = (const float*)d_in[8];
    const float* W_hh      = (const float*)d_in[9];
    const float* b_ih      = (const float*)d_in[10];
    const float* b_hh      = (const float*)d_in[11];
    const float* W_a       = (const float*)d_in[12];
    const float* W_out     = (const float*)d_in[13];
    const float* b_out     = (const float*)d_in[14];
    float* out = (float*)d_out;

    cudaFuncSetAttribute(gemm_logits, cudaFuncAttributeMaxDynamicSharedMemorySize, GM_SMEM);
    cudaFuncSetAttribute(gemm_q,      cudaFuncAttributeMaxDynamicSharedMemorySize, GM_SMEM);
    cudaFuncSetAttribute(gemm_gigh,   cudaFuncAttributeMaxDynamicSharedMemorySize, GM_SMEM);

    __nv_bfloat16 *pWih, *pWhh, *pWa, *pWout, *pxt, *pht, *pvt;
    float *p_a0, *p_h;
    cudaGetSymbolAddress((void**)&pWih,  g_Wih);
    cudaGetSymbolAddress((void**)&pWhh,  g_Whh);
    cudaGetSymbolAddress((void**)&pWa,   g_Wa);
    cudaGetSymbolAddress((void**)&pWout, g_Wout);
    cudaGetSymbolAddress((void**)&pxt,   g_xt);
    cudaGetSymbolAddress((void**)&pht,   g_ht);
    cudaGetSymbolAddress((void**)&pvt,   g_vt);
    cudaGetSymbolAddress((void**)&p_a0,  g_a0);
    cudaGetSymbolAddress((void**)&p_h,   g_h);

    // launch 0: all weight conversion (tiled + swizzled layout)
    convert_all<<<NB_CONV, 256>>>(W_ih, W_hh, W_a, W_out);
    // launch 1: a0 + x0
    build_init<<<(BB * 192 + BB * EE + 255) / 256, 256>>>(latent, style, style_emb, emb);
    // launch 2: h init (+ tiled split)
    gemm_init<<<HH / 128, 128>>>(p_a0, 192, W_l2h, b_l2h, p_h, HH, 192);

    // decode loop
    for (int t = 0; t < STEPS; t++) {
        gemm_gigh<<<192, 512, GM_SMEM>>>(pxt, pWih, pht, pWhh);
        gru_gates<<<(BB * HH) / 256, 256>>>(b_ih, b_hh);
        gemm_q<<<64, 512, GM_SMEM>>>(pht, pWa);
        attn_kernel<<<BB, 512>>>(enc);
        gemm_logits<<<VV / 128, 512, GM_SMEM>>>(pvt, pWout, b_out,
                                                out + (size_t)t * VV, (long)STEPS * VV);
        if (t < STEPS - 1) argmax_embed<<<BB, 512>>>(out + (size_t)t * VV, emb);
    }
}

// round 12
// speedup vs baseline: 2.2477x; 1.1137x over previous
#include <cuda_runtime.h>
#include <cuda_bf16.h>
#include <math.h>

// Problem constants
#define BB 64
#define HH 1024
#define EE 512
#define VV 32000
#define TENC 64
#define STEPS 32
#define KOUT 2048   // 2*H

typedef unsigned long long ull;
typedef unsigned int u32;

// ---------------- scratch (device globals; no allocation allowed) ----------
__device__ float g_a0[BB * 192];
__device__ float g_h[BB * HH];            // fp32 master hidden state
__device__ float g_gip[4][BB * 3 * HH];   // split-K partials of x @ W_ih^T
__device__ float g_ghp[8][BB * 3 * HH];   // split-K partials of h @ W_hh^T
__device__ float g_qp[8][BB * HH];        // split-K partials of h @ W_a

// Tiled+swizzled activations: [kchunk][64 rows x 128B(32hi|32lo)] = 8KB blocks
__device__ __align__(16) __nv_bfloat16 g_xt[BB * EE * 2];     // 16 chunks
__device__ __align__(16) __nv_bfloat16 g_ht[BB * HH * 2];     // 32 chunks
__device__ __align__(16) __nv_bfloat16 g_vt[BB * KOUT * 2];   // 64 chunks

// Tiled+swizzled weights: [ntile][kchunk][128 rows x 128B(32hi|32lo)] = 16KB blocks
__device__ __align__(16) __nv_bfloat16 g_Wih[3 * HH * 2 * EE];
__device__ __align__(16) __nv_bfloat16 g_Whh[3 * HH * 2 * HH];
__device__ __align__(16) __nv_bfloat16 g_Wa[HH * 2 * HH];
__device__ __align__(16) __nv_bfloat16 g_Wout[(size_t)VV * 2 * KOUT];

// ====================== PTX helpers ========================================
__device__ __forceinline__ u32 smem_u32(const void* p) {
    u32 a;
    asm("{ .reg .u64 t; cvta.to.shared.u64 t, %1; cvt.u32.u64 %0, t; }"
        : "=r"(a) : "l"(p));
    return a;
}
#define MBAR_INIT(a, c) \
    asm volatile("mbarrier.init.shared.b64 [%0], %1;" :: "r"(a), "r"(c) : "memory")
#define MBAR_EXPECT(a, b) \
    asm volatile("mbarrier.arrive.expect_tx.shared.b64 _, [%0], %1;" :: "r"(a), "r"(b) : "memory")
#define MBAR_ARRIVE(a) \
    asm volatile("mbarrier.arrive.shared.b64 _, [%0];" :: "r"(a) : "memory")
#define FENCE_ASYNC() \
    asm volatile("fence.proxy.async.shared::cta;" ::: "memory")
#define BULK_G2S(dst, src, sz, mb) \
    asm volatile("cp.async.bulk.shared::cluster.global.mbarrier::complete_tx::bytes " \
                 "[%0], [%1], %2, [%3];" \
                 :: "r"(dst), "l"(src), "r"(sz), "r"(mb) : "memory")

__device__ __forceinline__ void mbar_wait(u32 addr, u32 parity) {
    asm volatile(
        "{\n\t.reg .pred P;\n\t"
        "W%=:\n\t"
        "mbarrier.try_wait.parity.shared.b64 P, [%0], %1;\n\t"
        "@P bra D%=;\n\t"
        "bra W%=;\n\t"
        "D%=:\n\t}"
        :: "r"(addr), "r"(parity) : "memory");
}
__device__ __forceinline__ void ldmx4(u32* r, u32 addr) {
    asm volatile("ldmatrix.sync.aligned.m8n8.x4.shared.b16 {%0,%1,%2,%3}, [%4];"
                 : "=r"(r[0]), "=r"(r[1]), "=r"(r[2]), "=r"(r[3]) : "r"(addr));
}
__device__ __forceinline__ void mma16816(float* c, const u32* a, const u32* b) {
    asm volatile(
        "mma.sync.aligned.m16n8k16.row.col.f32.bf16.bf16.f32 "
        "{%0,%1,%2,%3}, {%4,%5,%6,%7}, {%8,%9}, {%0,%1,%2,%3};"
        : "+f"(c[0]), "+f"(c[1]), "+f"(c[2]), "+f"(c[3])
        : "r"(a[0]), "r"(a[1]), "r"(a[2]), "r"(a[3]), "r"(b[0]), "r"(b[1]));
}

// ===========================================================================
// Split-bf16 HMMA GEMM body (512 threads, 16 warps):
//   C[64, N] = (Ah+Al)[64,Klen] @ (Bh+Bl)[N,Klen]^T (+ bias)
//   = Ah·Bh + Al·Bh + Ah·Bl  (Al·Bl dropped, ~2^-16 relative)
// A/B pre-tiled + SW128-swizzled in GMEM; loaded via 2 cp.async.bulk per stage.
// 4-stage pipeline with per-stage full/empty mbarriers — NO per-chunk
// __syncthreads; thread 0 is the producer, paced by empty[s].
// CTA tile 64 x 128; warp grid 2m x 8n; warp tile 32 x 16. nk >= 4.
// ===========================================================================
#define ABLK 8192
#define BBLK 16384
#define STGSZ (ABLK + BBLK)          // 24576
#define NSTG 4
#define GM_SMEM (NSTG * STGSZ + 64)  // 98368

__device__ __forceinline__ void gemm_body(
    const __nv_bfloat16* __restrict__ At, const __nv_bfloat16* __restrict__ Bt,
    const float* __restrict__ bias, float* __restrict__ C,
    long ldc, int nk, int nkTot, int kcBase, int ntile, char* smem)
{
    const u32 sb = smem_u32(smem);
    const u32 mbF = sb + NSTG * STGSZ;   // full[0..3], 8B each
    const u32 mbE = mbF + 32;            // empty[0..3]
    const int tid = threadIdx.x, wid = tid >> 5, lane = tid & 31;
    const int wm = (wid & 1) * 32;       // warp m offset: 0 or 32
    const int wn = (wid >> 1) * 16;      // warp n offset: 0..112
    const int n_cta = ntile * 128;

    if (tid == 0) {
#pragma unroll
        for (int s = 0; s < NSTG; s++) {
            MBAR_INIT(mbF + 8 * s, 1);
            MBAR_INIT(mbE + 8 * s, 16);
        }
    }
    FENCE_ASYNC();
    __syncthreads();

    const char* Ab = (const char*)At + (size_t)kcBase * ABLK;
    const char* Bb = (const char*)Bt + ((size_t)ntile * nkTot + kcBase) * BBLK;

    if (tid == 0) {
#pragma unroll
        for (int j = 0; j < NSTG; j++) {   // nk >= 4 always
            u32 m = mbF + 8 * j;
            MBAR_EXPECT(m, STGSZ);
            BULK_G2S(sb + j * STGSZ,        Ab + (size_t)j * ABLK, ABLK, m);
            BULK_G2S(sb + j * STGSZ + ABLK, Bb + (size_t)j * BBLK, BBLK, m);
        }
    }

    float acc[2][2][4] = {};

    const int lrow = lane & 15;
    const int lkof = (lane >> 4) * 16;
    // swizzled row bases: addr = rowbase + (colbyte ^ xm), xm = (row&7)<<4
    const int a0r = wm + lrow,  a1r = wm + 16 + lrow,  brr = wn + lrow;
    const u32 a0b = a0r * 128,  a0x = (a0r & 7) << 4;
    const u32 a1b = a1r * 128,  a1x = (a1r & 7) << 4;
    const u32 brb = brr * 128,  brx = (brr & 7) << 4;

    for (int j = 0; j < nk; j++) {
        const int s = j & (NSTG - 1);
        const u32 ph = (j >> 2) & 1;
        mbar_wait(mbF + 8 * s, ph);

        const u32 bbA = sb + s * STGSZ;
        const u32 bbB = bbA + ABLK;
#pragma unroll
        for (int ks = 0; ks < 2; ks++) {
            const u32 o = ks * 32 + lkof;
            u32 ah[2][4], al[2][4], bh[4], bl[4];
            ldmx4(ah[0], bbA + a0b + (o ^ a0x));
            ldmx4(ah[1], bbA + a1b + (o ^ a1x));
            ldmx4(al[0], bbA + a0b + ((o + 64) ^ a0x));
            ldmx4(al[1], bbA + a1b + ((o + 64) ^ a1x));
            ldmx4(bh,    bbB + brb + (o ^ brx));
            ldmx4(bl,    bbB + brb + ((o + 64) ^ brx));

            u32 b0h[2] = { bh[0], bh[2] };
            u32 b1h[2] = { bh[1], bh[3] };
            u32 b0l[2] = { bl[0], bl[2] };
            u32 b1l[2] = { bl[1], bl[3] };
#pragma unroll
            for (int mt = 0; mt < 2; mt++) {
                float* c0 = acc[mt][0];
                float* c1 = acc[mt][1];
                mma16816(c0, ah[mt], b0h);
                mma16816(c1, ah[mt], b1h);
                mma16816(c0, al[mt], b0h);
                mma16816(c1, al[mt], b1h);
                mma16816(c0, ah[mt], b0l);
                mma16816(c1, ah[mt], b1l);
            }
        }
        // this warp is done reading stage s
        if (lane == 0) MBAR_ARRIVE(mbE + 8 * s);

        // producer: refill stage s with chunk j+4 once all 16 warps released it
        if (tid == 0 && j + NSTG < nk) {
            mbar_wait(mbE + 8 * s, ph);
            u32 m = mbF + 8 * s;
            MBAR_EXPECT(m, STGSZ);
            BULK_G2S(sb + s * STGSZ,        Ab + (size_t)(j + NSTG) * ABLK, ABLK, m);
            BULK_G2S(sb + s * STGSZ + ABLK, Bb + (size_t)(j + NSTG) * BBLK, BBLK, m);
        }
    }

    // Epilogue: frag (mt, t): rows wm+mt*16+{l/4, l/4+8}, cols wn+t*8+2*(l%4)
#pragma unroll
    for (int mt = 0; mt < 2; mt++) {
        int m = wm + mt * 16 + (lane >> 2);
#pragma unroll
        for (int t = 0; t < 2; t++) {
            int n = n_cta + wn + t * 8 + 2 * (lane & 3);
            float* a = acc[mt][t];
            float b0 = bias ? bias[n] : 0.f;
            float b1 = bias ? bias[n + 1] : 0.f;
            float2 v0 = { a[0] + b0, a[1] + b1 };
            float2 v1 = { a[2] + b0, a[3] + b1 };
            *reinterpret_cast<float2*>(C + (size_t)m * ldc + n) = v0;
            *reinterpret_cast<float2*>(C + (size_t)(m + 8) * ldc + n) = v1;
        }
    }
}

// logits GEMM: 250 CTAs
__global__ __launch_bounds__(512, 2)
void gemm_logits(const __nv_bfloat16* __restrict__ At, const __nv_bfloat16* __restrict__ Bt,
                 const float* __restrict__ bias, float* __restrict__ C, long ldc)
{
    extern __shared__ char smem[];
    gemm_body(At, Bt, bias, C, ldc, KOUT / 32, KOUT / 32, 0, blockIdx.x, smem);
}

// q-GEMM 8-way split-K: 64 CTAs; slice s covers chunks [s*4, s*4+4)
__global__ __launch_bounds__(512, 2)
void gemm_q(const __nv_bfloat16* __restrict__ ht, const __nv_bfloat16* __restrict__ Wa)
{
    extern __shared__ char smem[];
    int s = blockIdx.x >> 3, nt = blockIdx.x & 7;
    gemm_body(ht, Wa, nullptr, g_qp[s], HH, 4, HH / 32, s * 4, nt, smem);
}

// fused gi + gh: gi 4-way split (96 CTAs), gh 8-way split (192 CTAs) = 288 CTAs
// every CTA processes exactly 4 chunks (balanced)
__global__ __launch_bounds__(512, 2)
void gemm_gigh(const __nv_bfloat16* __restrict__ xt, const __nv_bfloat16* __restrict__ Wih,
               const __nv_bfloat16* __restrict__ ht, const __nv_bfloat16* __restrict__ Whh)
{
    extern __shared__ char smem[];
    int bid = blockIdx.x;
    if (bid < 96) {
        int s = bid / 24, nt = bid % 24;   // gi: K=512 -> 4 slices x 4 chunks
        gemm_body(xt, Wih, nullptr, g_gip[s], 3 * HH, 4, EE / 32, s * 4, nt, smem);
    } else {
        bid -= 96;
        int s = bid / 24, nt = bid % 24;   // gh: K=1024 -> 8 slices x 4 chunks
        gemm_body(ht, Whh, nullptr, g_ghp[s], 3 * HH, 4, HH / 32, s * 4, nt, smem);
    }
}

// ===================== split + tiled-store helpers =========================
__device__ __forceinline__ void split2(float v, __nv_bfloat16& h, __nv_bfloat16& l) {
    h = __float2bfloat16(v);
    l = __float2bfloat16(v - __bfloat162float(h));
}

// store one activation element into tiled+swizzled layout (8KB A-blocks)
__device__ __forceinline__ void store_act(__nv_bfloat16* base, int kc, int r, int c, float v) {
    __nv_bfloat16 h, l; split2(v, h, l);
    u32 xm = (r & 7) << 4;
    char* p = (char*)base + (size_t)kc * ABLK + r * 128;
    *reinterpret_cast<__nv_bfloat16*>(p + ((c * 2) ^ xm)) = h;
    *reinterpret_cast<__nv_bfloat16*>(p + ((64 + c * 2) ^ xm)) = l;
}

// store one weight element into tiled+swizzled layout (16KB B-blocks)
__device__ __forceinline__ void store_w(__nv_bfloat16* base, int nkTot, int n, int k, float v) {
    __nv_bfloat16 h, l; split2(v, h, l);
    int nt = n >> 7, r = n & 127, kc = k >> 5, c = k & 31;
    u32 xm = (r & 7) << 4;
    char* p = (char*)base + ((size_t)nt * nkTot + kc) * BBLK + r * 128;
    *reinterpret_cast<__nv_bfloat16*>(p + ((c * 2) ^ xm)) = h;
    *reinterpret_cast<__nv_bfloat16*>(p + ((64 + c * 2) ^ xm)) = l;
}

// elementwise: src already [N,K]
__device__ __forceinline__ void esplit_blk(const float* src, __nv_bfloat16* dc,
                                           int K, int bi, int tid)
{
    int i = bi * 256 + tid;
    store_w(dc, K >> 5, i / K, i % K, src[i]);
}

// transpose 32x32 tile: src [K,N] fp32 -> tiled [N-major] layout
__device__ __forceinline__ void tsplit_blk(const float* src, __nv_bfloat16* dc,
                                           int K, int N, int bx, int by, int tid)
{
    __shared__ float t[32][33];
    int k0 = by * 32, n0 = bx * 32;
    int tx = tid & 31, ty = tid >> 5;   // 32 x 8
#pragma unroll
    for (int i = ty; i < 32; i += 8)
        t[i][tx] = src[(size_t)(k0 + i) * N + n0 + tx];
    __syncthreads();
#pragma unroll
    for (int i = ty; i < 32; i += 8)
        store_w(dc, K >> 5, n0 + i, k0 + tx, t[tx][i]);
}

#define NB_WIH  6144    // 3*HH*EE / 256
#define NB_WHH 12288    // 3*HH*HH / 256
#define NB_WA   1024    // (HH/32)*(HH/32)
#define NB_WOUT 64000   // (VV/32)*(KOUT/32)
#define NB_CONV (NB_WIH + NB_WHH + NB_WA + NB_WOUT)

__global__ __launch_bounds__(256)
void convert_all(const float* __restrict__ W_ih, const float* __restrict__ W_hh,
                 const float* __restrict__ W_a,  const float* __restrict__ W_out)
{
    int b = blockIdx.x, tid = threadIdx.x;
    if (b < NB_WIH) {
        esplit_blk(W_ih, g_Wih, EE, b, tid);
    } else if (b < NB_WIH + NB_WHH) {
        esplit_blk(W_hh, g_Whh, HH, b - NB_WIH, tid);
    } else if (b < NB_WIH + NB_WHH + NB_WA) {
        int bi = b - NB_WIH - NB_WHH;
        tsplit_blk(W_a, g_Wa, HH, HH, bi % 32, bi / 32, tid);
    } else {
        int bi = b - NB_WIH - NB_WHH - NB_WA;
        tsplit_blk(W_out, g_Wout, KOUT, VV, bi % (VV / 32), bi / (VV / 32), tid);
    }
}

// ======================= init kernels ======================================
__global__ void build_init(const float* __restrict__ latent,
                           const int* __restrict__ style,
                           const float* __restrict__ style_emb,
                           const float* __restrict__ emb)
{
    int idx = blockIdx.x * blockDim.x + threadIdx.x;
    if (idx < BB * 192) {
        int b = idx / 192, k = idx - b * 192;
        g_a0[idx] = (k < 128) ? latent[b * 128 + k]
                              : style_emb[style[b] * 64 + (k - 128)];
    } else {
        int i = idx - BB * 192;
        if (i < BB * EE) {
            int b = i >> 9, e = i & (EE - 1);
            float v = emb[EE /* BOS=1 row */ + e];
            store_act(g_xt, e >> 5, b, e & 31, v);
        }
    }
}

// h = a0 @ W_l2h + b (fp32 FFMA; also emits tiled split-bf16 h)
__global__ __launch_bounds__(128)
void gemm_init(const float* __restrict__ A, int lda,
               const float* __restrict__ Bm, const float* __restrict__ bias,
               float* __restrict__ C, int N, int K)
{
    __shared__ float As[16][68];
    __shared__ float Bs[16][132];
    const int tid = threadIdx.x;
    const int n0 = blockIdx.x * 128;
    const int tm = (tid >> 4) << 3, tn = (tid & 15) << 3;
    float acc[8][8] = {};
    for (int k0 = 0; k0 < K; k0 += 16) {
        {
            int k = tid & 15, m = tid >> 4;
#pragma unroll
            for (int i = 0; i < 8; i++)
                As[k][m + i * 8] = A[(m + i * 8) * lda + k0 + k];
        }
        {
            int w = tid >> 5, n4 = (tid & 31) << 2;
#pragma unroll
            for (int kb = 0; kb < 4; kb++) {
                int k = kb * 4 + w;
                *reinterpret_cast<float4*>(&Bs[k][n4]) =
                    *reinterpret_cast<const float4*>(&Bm[(size_t)(k0 + k) * N + n0 + n4]);
            }
        }
        __syncthreads();
#pragma unroll
        for (int kk = 0; kk < 16; kk++) {
#pragma unroll
            for (int i = 0; i < 8; i++) {
                float a = As[kk][tm + i];
#pragma unroll
                for (int j = 0; j < 8; j++) acc[i][j] += a * Bs[kk][tn + j];
            }
        }
        __syncthreads();
    }
#pragma unroll
    for (int i = 0; i < 8; i++)
#pragma unroll
        for (int j = 0; j < 8; j++) {
            int n = n0 + tn + j;
            float v = acc[i][j] + (bias ? bias[n] : 0.f);
            int m = tm + i;
            C[(size_t)m * N + n] = v;
            store_act(g_ht, n >> 5, m, n & 31, v);
        }
}

// ========================= per-step small kernels ==========================
__global__ void gru_gates(const float* __restrict__ b_ih, const float* __restrict__ b_hh)
{
    int idx = blockIdx.x * blockDim.x + threadIdx.x;   // 64*1024
    int b = idx >> 10, j = idx & 1023;
    int base = b * 3 * HH + j;
    float ir = b_ih[j], iz = b_ih[j + HH], in = b_ih[j + 2 * HH];
    float hr = b_hh[j], hz = b_hh[j + HH], hn = b_hh[j + 2 * HH];
#pragma unroll
    for (int s = 0; s < 4; s++) {
        ir += g_gip[s][base];
        iz += g_gip[s][base + HH];
        in += g_gip[s][base + 2 * HH];
    }
#pragma unroll
    for (int s = 0; s < 8; s++) {
        hr += g_ghp[s][base];
        hz += g_ghp[s][base + HH];
        hn += g_ghp[s][base + 2 * HH];
    }
    float r = 1.f / (1.f + expf(-(ir + hr)));
    float z = 1.f / (1.f + expf(-(iz + hz)));
    float n = tanhf(in + r * hn);
    float hnew = (1.f - z) * n + z * g_h[idx];
    g_h[idx] = hnew;
    int kc = j >> 5, c = j & 31;
    store_act(g_ht, kc, b, c, hnew);
    store_act(g_vt, kc, b, c, hnew);   // vcat chunks 0..31 = h
}

__global__ __launch_bounds__(512)
void attn_kernel(const float* __restrict__ enc)
{
    int b = blockIdx.x;
    int tid = threadIdx.x;              // 512
    __shared__ float s_q[HH];
    __shared__ float s_scores[TENC];
    __shared__ float s_attn[TENC];

    for (int i = tid; i < HH; i += 512) {
        int o = b * HH + i;
        float q = 0.f;
#pragma unroll
        for (int s = 0; s < 8; s++) q += g_qp[s][o];
        s_q[i] = q;
    }
    __syncthreads();

    int warp = tid >> 5, lane = tid & 31;
    for (int t = warp; t < TENC; t += 16) {
        const float* e = enc + ((size_t)b * TENC + t) * HH;
        float s = 0.f;
        for (int h = lane; h < HH; h += 32) s += s_q[h] * e[h];
#pragma unroll
        for (int o = 16; o; o >>= 1) s += __shfl_xor_sync(0xFFFFFFFFu, s, o);
        if (lane == 0) s_scores[t] = s;
    }
    __syncthreads();

    float mx = -1e30f;
    for (int t = 0; t < TENC; t++) mx = fmaxf(mx, s_scores[t]);
    if (tid < TENC) s_attn[tid] = expf(s_scores[tid] - mx);
    __syncthreads();
    float ssum = 0.f;
    for (int t = 0; t < TENC; t++) ssum += s_attn[t];
    float inv = 1.f / ssum;

    for (int h = tid; h < HH; h += 512) {
        float c = 0.f;
        const float* eb = enc + (size_t)b * TENC * HH + h;
#pragma unroll 8
        for (int t = 0; t < TENC; t++) c += s_attn[t] * eb[(size_t)t * HH];
        c *= inv;
        store_act(g_vt, 32 + (h >> 5), b, h & 31, c);   // vcat chunks 32..63 = ctx
    }
}

__global__ __launch_bounds__(512)
void argmax_embed(const float* __restrict__ logits_t,
                  const float* __restrict__ emb)
{
    int b = blockIdx.x;
    int tid = threadIdx.x;              // 512
    const float* L = logits_t + (size_t)b * STEPS * VV;

    float best = -1e30f; int bi = VV;
    for (int n = tid; n < VV; n += 512) {
        float v = L[n];
        if (v > best) { best = v; bi = n; }
    }
    __shared__ float sv[512]; __shared__ int si[512];
    sv[tid] = best; si[tid] = bi;
    __syncthreads();
    for (int s = 256; s; s >>= 1) {
        if (tid < s) {
            if (sv[tid + s] > sv[tid] ||
                (sv[tid + s] == sv[tid] && si[tid + s] < si[tid])) {
                sv[tid] = sv[tid + s]; si[tid] = si[tid + s];
            }
        }
        __syncthreads();
    }
    int tok = si[0];
    for (int e = tid; e < EE; e += 512) {
        float v = emb[(size_t)tok * EE + e];
        store_act(g_xt, e >> 5, b, e & 31, v);
    }
}

// ===========================================================================
extern "C" void kernel_launch(void* const* d_in, const int* in_sizes, int n_in,
                              void* d_out, int out_size)
{
    const float* latent    = (const float*)d_in[0];
    const int*   style     = (const int*)  d_in[1];
    const float* enc       = (const float*)d_in[2];
    const float* emb       = (const float*)d_in[4];
    const float* style_emb = (const float*)d_in[5];
    const float* W_l2h     = (const float*)d_in[6];
    const float* b_l2h     = (const float*)d_in[7];
    const float* W_ih      = (const float*)d_in[8];
    const float* W_hh      = (const float*)d_in[9];
    const float* b_ih      = (const float*)d_in[10];
    const float* b_hh      = (const float*)d_in[11];
    const float* W_a       = (const float*)d_in[12];
    const float* W_out     = (const float*)d_in[13];
    const float* b_out     = (const float*)d_in[14];
    float* out = (float*)d_out;

    cudaFuncSetAttribute(gemm_logits, cudaFuncAttributeMaxDynamicSharedMemorySize, GM_SMEM);
    cudaFuncSetAttribute(gemm_q,      cudaFuncAttributeMaxDynamicSharedMemorySize, GM_SMEM);
    cudaFuncSetAttribute(gemm_gigh,   cudaFuncAttributeMaxDynamicSharedMemorySize, GM_SMEM);

    __nv_bfloat16 *pWih, *pWhh, *pWa, *pWout, *pxt, *pht, *pvt;
    float *p_a0, *p_h;
    cudaGetSymbolAddress((void**)&pWih,  g_Wih);
    cudaGetSymbolAddress((void**)&pWhh,  g_Whh);
    cudaGetSymbolAddress((void**)&pWa,   g_Wa);
    cudaGetSymbolAddress((void**)&pWout, g_Wout);
    cudaGetSymbolAddress((void**)&pxt,   g_xt);
    cudaGetSymbolAddress((void**)&pht,   g_ht);
    cudaGetSymbolAddress((void**)&pvt,   g_vt);
    cudaGetSymbolAddress((void**)&p_a0,  g_a0);
    cudaGetSymbolAddress((void**)&p_h,   g_h);

    // launch 0: all weight conversion (tiled + swizzled layout)
    convert_all<<<NB_CONV, 256>>>(W_ih, W_hh, W_a, W_out);
    // launch 1: a0 + x0
    build_init<<<(BB * 192 + BB * EE + 255) / 256, 256>>>(latent, style, style_emb, emb);
    // launch 2: h init (+ tiled split)
    gemm_init<<<HH / 128, 128>>>(p_a0, 192, W_l2h, b_l2h, p_h, HH, 192);

    // decode loop
    for (int t = 0; t < STEPS; t++) {
        gemm_gigh<<<288, 512, GM_SMEM>>>(pxt, pWih, pht, pWhh);
        gru_gates<<<(BB * HH) / 256, 256>>>(b_ih, b_hh);
        gemm_q<<<64, 512, GM_SMEM>>>(pht, pWa);
        attn_kernel<<<BB, 512>>>(enc);
        gemm_logits<<<VV / 128, 512, GM_SMEM>>>(pvt, pWout, b_out,
                                                out + (size_t)t * VV, (long)STEPS * VV);
        if (t < STEPS - 1) argmax_embed<<<BB, 512>>>(out + (size_t)t * VV, emb);
    }
}

// round 13
// speedup vs baseline: 2.4174x; 1.0755x over previous
#include <cuda_runtime.h>
#include <cuda_bf16.h>
#include <math.h>

// Problem constants
#define BB 64
#define HH 1024
#define EE 512
#define VV 32000
#define TENC 64
#define STEPS 32
#define KOUT 2048   // 2*H

typedef unsigned long long ull;
typedef unsigned int u32;

// ---------------- scratch (device globals; no allocation allowed) ----------
__device__ float g_a0[BB * 192];
__device__ float g_h[BB * HH];            // fp32 master hidden state
__device__ float g_gip[4][BB * 3 * HH];   // split-K partials of x @ W_ih^T
__device__ float g_ghp[8][BB * 3 * HH];   // split-K partials of h @ W_hh^T
__device__ float g_qp[8][BB * HH];        // split-K partials of h @ W_a
__device__ ull   g_amax[BB];              // packed (key, 0x7FFFFFFF-n) argmax

// Tiled+swizzled activations: [kchunk][64 rows x 128B(32hi|32lo)] = 8KB blocks
__device__ __align__(16) __nv_bfloat16 g_xt[BB * EE * 2];     // 16 chunks
__device__ __align__(16) __nv_bfloat16 g_ht[BB * HH * 2];     // 32 chunks
__device__ __align__(16) __nv_bfloat16 g_vt[BB * KOUT * 2];   // 64 chunks

// Tiled+swizzled weights: [ntile][kchunk][128 rows x 128B(32hi|32lo)] = 16KB blocks
__device__ __align__(16) __nv_bfloat16 g_Wih[3 * HH * 2 * EE];
__device__ __align__(16) __nv_bfloat16 g_Whh[3 * HH * 2 * HH];
__device__ __align__(16) __nv_bfloat16 g_Wa[HH * 2 * HH];
__device__ __align__(16) __nv_bfloat16 g_Wout[(size_t)VV * 2 * KOUT];

// ====================== PTX helpers ========================================
__device__ __forceinline__ u32 smem_u32(const void* p) {
    u32 a;
    asm("{ .reg .u64 t; cvta.to.shared.u64 t, %1; cvt.u32.u64 %0, t; }"
        : "=r"(a) : "l"(p));
    return a;
}
#define MBAR_INIT(a, c) \
    asm volatile("mbarrier.init.shared.b64 [%0], %1;" :: "r"(a), "r"(c) : "memory")
#define MBAR_EXPECT(a, b) \
    asm volatile("mbarrier.arrive.expect_tx.shared.b64 _, [%0], %1;" :: "r"(a), "r"(b) : "memory")
#define MBAR_ARRIVE(a) \
    asm volatile("mbarrier.arrive.shared.b64 _, [%0];" :: "r"(a) : "memory")
#define FENCE_ASYNC() \
    asm volatile("fence.proxy.async.shared::cta;" ::: "memory")
#define BULK_G2S(dst, src, sz, mb) \
    asm volatile("cp.async.bulk.shared::cluster.global.mbarrier::complete_tx::bytes " \
                 "[%0], [%1], %2, [%3];" \
                 :: "r"(dst), "l"(src), "r"(sz), "r"(mb) : "memory")

__device__ __forceinline__ void mbar_wait(u32 addr, u32 parity) {
    asm volatile(
        "{\n\t.reg .pred P;\n\t"
        "W%=:\n\t"
        "mbarrier.try_wait.parity.shared.b64 P, [%0], %1;\n\t"
        "@P bra D%=;\n\t"
        "bra W%=;\n\t"
        "D%=:\n\t}"
        :: "r"(addr), "r"(parity) : "memory");
}
__device__ __forceinline__ void ldmx4(u32* r, u32 addr) {
    asm volatile("ldmatrix.sync.aligned.m8n8.x4.shared.b16 {%0,%1,%2,%3}, [%4];"
                 : "=r"(r[0]), "=r"(r[1]), "=r"(r[2]), "=r"(r[3]) : "r"(addr));
}
__device__ __forceinline__ void mma16816(float* c, const u32* a, const u32* b) {
    asm volatile(
        "mma.sync.aligned.m16n8k16.row.col.f32.bf16.bf16.f32 "
        "{%0,%1,%2,%3}, {%4,%5,%6,%7}, {%8,%9}, {%0,%1,%2,%3};"
        : "+f"(c[0]), "+f"(c[1]), "+f"(c[2]), "+f"(c[3])
        : "r"(a[0]), "r"(a[1]), "r"(a[2]), "r"(a[3]), "r"(b[0]), "r"(b[1]));
}

// packed argmax key: monotone float map in hi 32, (0x7FFFFFFF - n) in lo 32
__device__ __forceinline__ ull amax_pack(float v, int n) {
    u32 b = __float_as_uint(v);
    u32 key = (b & 0x80000000u) ? ~b : (b | 0x80000000u);
    return ((ull)key << 32) | (ull)(0x7FFFFFFFu - (u32)n);
}

// ===========================================================================
// Split-bf16 HMMA GEMM body (544 threads = 16 consumer warps + 1 producer):
//   C[64, N] = (Ah+Al)[64,Klen] @ (Bh+Bl)[N,Klen]^T (+ bias)
//   = Ah·Bh + Al·Bh + Ah·Bl  (Al·Bl dropped, ~2^-16 relative)
// A/B pre-tiled + SW128-swizzled in GMEM; loaded via 2 cp.async.bulk per stage.
// 4-stage pipeline, full/empty mbarriers; warp 16 lane 0 is dedicated producer.
// CTA tile 64 x 128; consumer warp grid 2m x 8n; warp tile 32 x 16. nk >= 4.
// AM=1: additionally computes per-row argmax of biased output into g_amax.
// ===========================================================================
#define ABLK 8192
#define BBLK 16384
#define STGSZ (ABLK + BBLK)                 // 24576
#define NSTG 4
#define GM_SMEM (NSTG * STGSZ + 64 + 512)   // stages + mbarriers + best[64]

template <int AM>
__device__ __forceinline__ void gemm_body(
    const __nv_bfloat16* __restrict__ At, const __nv_bfloat16* __restrict__ Bt,
    const float* __restrict__ bias, float* __restrict__ C,
    long ldc, int nk, int nkTot, int kcBase, int ntile, char* smem)
{
    const u32 sb = smem_u32(smem);
    const u32 mbF = sb + NSTG * STGSZ;   // full[0..3], 8B each
    const u32 mbE = mbF + 32;            // empty[0..3]
    const int tid = threadIdx.x, wid = tid >> 5, lane = tid & 31;
    const int wm = (wid & 1) * 32;       // warp m offset: 0 or 32
    const int wn = (wid >> 1) * 16;      // warp n offset: 0..112
    const int n_cta = ntile * 128;

    if (tid == 0) {
#pragma unroll
        for (int s = 0; s < NSTG; s++) {
            MBAR_INIT(mbF + 8 * s, 1);
            MBAR_INIT(mbE + 8 * s, 16);
        }
    }
    FENCE_ASYNC();
    __syncthreads();

    float acc[2][2][4] = {};

    if (wid == 16) {
        // ---------------- producer warp (lane 0 only) ----------------
        if (lane == 0) {
            const char* Ab = (const char*)At + (size_t)kcBase * ABLK;
            const char* Bb = (const char*)Bt + ((size_t)ntile * nkTot + kcBase) * BBLK;
            for (int j = 0; j < nk; j++) {
                const int s = j & (NSTG - 1);
                if (j >= NSTG) mbar_wait(mbE + 8 * s, ((j - NSTG) >> 2) & 1);
                u32 m = mbF + 8 * s;
                MBAR_EXPECT(m, STGSZ);
                BULK_G2S(sb + s * STGSZ,        Ab + (size_t)j * ABLK, ABLK, m);
                BULK_G2S(sb + s * STGSZ + ABLK, Bb + (size_t)j * BBLK, BBLK, m);
            }
        }
    } else {
        // ---------------- consumer warps ----------------
        const int lrow = lane & 15;
        const int lkof = (lane >> 4) * 16;
        const int a0r = wm + lrow,  a1r = wm + 16 + lrow,  brr = wn + lrow;
        const u32 a0b = a0r * 128,  a0x = (a0r & 7) << 4;
        const u32 a1b = a1r * 128,  a1x = (a1r & 7) << 4;
        const u32 brb = brr * 128,  brx = (brr & 7) << 4;

        for (int j = 0; j < nk; j++) {
            const int s = j & (NSTG - 1);
            mbar_wait(mbF + 8 * s, (j >> 2) & 1);

            const u32 bbA = sb + s * STGSZ;
            const u32 bbB = bbA + ABLK;
#pragma unroll
            for (int ks = 0; ks < 2; ks++) {
                const u32 o = ks * 32 + lkof;
                u32 ah[2][4], al[2][4], bh[4], bl[4];
                ldmx4(ah[0], bbA + a0b + (o ^ a0x));
                ldmx4(ah[1], bbA + a1b + (o ^ a1x));
                ldmx4(al[0], bbA + a0b + ((o + 64) ^ a0x));
                ldmx4(al[1], bbA + a1b + ((o + 64) ^ a1x));
                ldmx4(bh,    bbB + brb + (o ^ brx));
                ldmx4(bl,    bbB + brb + ((o + 64) ^ brx));

                u32 b0h[2] = { bh[0], bh[2] };
                u32 b1h[2] = { bh[1], bh[3] };
                u32 b0l[2] = { bl[0], bl[2] };
                u32 b1l[2] = { bl[1], bl[3] };
#pragma unroll
                for (int mt = 0; mt < 2; mt++) {
                    float* c0 = acc[mt][0];
                    float* c1 = acc[mt][1];
                    mma16816(c0, ah[mt], b0h);
                    mma16816(c1, ah[mt], b1h);
                    mma16816(c0, al[mt], b0h);
                    mma16816(c1, al[mt], b1h);
                    mma16816(c0, ah[mt], b0l);
                    mma16816(c1, ah[mt], b1l);
                }
            }
            if (lane == 0) MBAR_ARRIVE(mbE + 8 * s);
        }
    }

    // ------------- epilogue -------------
    ull* best = reinterpret_cast<ull*>(smem + NSTG * STGSZ + 64);
    if (AM) {
        if (tid < 64) best[tid] = 0;
        __syncthreads();
    }

    if (wid < 16) {
#pragma unroll
        for (int mt = 0; mt < 2; mt++) {
            int m = wm + mt * 16 + (lane >> 2);
            ull p0 = 0, p1 = 0;
#pragma unroll
            for (int t = 0; t < 2; t++) {
                int n = n_cta + wn + t * 8 + 2 * (lane & 3);
                float* a = acc[mt][t];
                float b0 = bias ? bias[n] : 0.f;
                float b1 = bias ? bias[n + 1] : 0.f;
                float2 v0 = { a[0] + b0, a[1] + b1 };
                float2 v1 = { a[2] + b0, a[3] + b1 };
                *reinterpret_cast<float2*>(C + (size_t)m * ldc + n) = v0;
                *reinterpret_cast<float2*>(C + (size_t)(m + 8) * ldc + n) = v1;
                if (AM) {
                    ull q0 = amax_pack(v0.x, n), q1 = amax_pack(v0.y, n + 1);
                    p0 = max(p0, max(q0, q1));
                    ull q2 = amax_pack(v1.x, n), q3 = amax_pack(v1.y, n + 1);
                    p1 = max(p1, max(q2, q3));
                }
            }
            if (AM) {
                // reduce across the 4 lanes sharing these rows
#pragma unroll
                for (int o = 1; o < 4; o <<= 1) {
                    p0 = max(p0, __shfl_xor_sync(0xFFFFFFFFu, p0, o));
                    p1 = max(p1, __shfl_xor_sync(0xFFFFFFFFu, p1, o));
                }
                if ((lane & 3) == 0) {
                    atomicMax(&best[m], p0);
                    atomicMax(&best[m + 8], p1);
                }
            }
        }
    }
    if (AM) {
        __syncthreads();
        if (tid < 64) atomicMax(&g_amax[tid], best[tid]);
    }
}

// logits GEMM: 250 CTAs, fused argmax
__global__ __launch_bounds__(544, 2)
void gemm_logits(const __nv_bfloat16* __restrict__ At, const __nv_bfloat16* __restrict__ Bt,
                 const float* __restrict__ bias, float* __restrict__ C, long ldc)
{
    extern __shared__ char smem[];
    gemm_body<1>(At, Bt, bias, C, ldc, KOUT / 32, KOUT / 32, 0, blockIdx.x, smem);
}

// q-GEMM 8-way split-K: 64 CTAs; slice s covers chunks [s*4, s*4+4)
__global__ __launch_bounds__(544, 2)
void gemm_q(const __nv_bfloat16* __restrict__ ht, const __nv_bfloat16* __restrict__ Wa)
{
    extern __shared__ char smem[];
    int s = blockIdx.x >> 3, nt = blockIdx.x & 7;
    gemm_body<0>(ht, Wa, nullptr, g_qp[s], HH, 4, HH / 32, s * 4, nt, smem);
}

// fused gi + gh: gi 4-way split (96 CTAs), gh 8-way split (192 CTAs) = 288 CTAs
__global__ __launch_bounds__(544, 2)
void gemm_gigh(const __nv_bfloat16* __restrict__ xt, const __nv_bfloat16* __restrict__ Wih,
               const __nv_bfloat16* __restrict__ ht, const __nv_bfloat16* __restrict__ Whh)
{
    extern __shared__ char smem[];
    int bid = blockIdx.x;
    if (bid < 96) {
        int s = bid / 24, nt = bid % 24;   // gi: K=512 -> 4 slices x 4 chunks
        gemm_body<0>(xt, Wih, nullptr, g_gip[s], 3 * HH, 4, EE / 32, s * 4, nt, smem);
    } else {
        bid -= 96;
        int s = bid / 24, nt = bid % 24;   // gh: K=1024 -> 8 slices x 4 chunks
        gemm_body<0>(ht, Whh, nullptr, g_ghp[s], 3 * HH, 4, HH / 32, s * 4, nt, smem);
    }
}

// ===================== split + tiled-store helpers =========================
__device__ __forceinline__ void split2(float v, __nv_bfloat16& h, __nv_bfloat16& l) {
    h = __float2bfloat16(v);
    l = __float2bfloat16(v - __bfloat162float(h));
}

// store one activation element into tiled+swizzled layout (8KB A-blocks)
__device__ __forceinline__ void store_act(__nv_bfloat16* base, int kc, int r, int c, float v) {
    __nv_bfloat16 h, l; split2(v, h, l);
    u32 xm = (r & 7) << 4;
    char* p = (char*)base + (size_t)kc * ABLK + r * 128;
    *reinterpret_cast<__nv_bfloat16*>(p + ((c * 2) ^ xm)) = h;
    *reinterpret_cast<__nv_bfloat16*>(p + ((64 + c * 2) ^ xm)) = l;
}

// store one weight element into tiled+swizzled layout (16KB B-blocks)
__device__ __forceinline__ void store_w(__nv_bfloat16* base, int nkTot, int n, int k, float v) {
    __nv_bfloat16 h, l; split2(v, h, l);
    int nt = n >> 7, r = n & 127, kc = k >> 5, c = k & 31;
    u32 xm = (r & 7) << 4;
    char* p = (char*)base + ((size_t)nt * nkTot + kc) * BBLK + r * 128;
    *reinterpret_cast<__nv_bfloat16*>(p + ((c * 2) ^ xm)) = h;
    *reinterpret_cast<__nv_bfloat16*>(p + ((64 + c * 2) ^ xm)) = l;
}

// elementwise: src already [N,K]
__device__ __forceinline__ void esplit_blk(const float* src, __nv_bfloat16* dc,
                                           int K, int bi, int tid)
{
    int i = bi * 256 + tid;
    store_w(dc, K >> 5, i / K, i % K, src[i]);
}

// transpose 32x32 tile: src [K,N] fp32 -> tiled [N-major] layout
__device__ __forceinline__ void tsplit_blk(const float* src, __nv_bfloat16* dc,
                                           int K, int N, int bx, int by, int tid)
{
    __shared__ float t[32][33];
    int k0 = by * 32, n0 = bx * 32;
    int tx = tid & 31, ty = tid >> 5;   // 32 x 8
#pragma unroll
    for (int i = ty; i < 32; i += 8)
        t[i][tx] = src[(size_t)(k0 + i) * N + n0 + tx];
    __syncthreads();
#pragma unroll
    for (int i = ty; i < 32; i += 8)
        store_w(dc, K >> 5, n0 + i, k0 + tx, t[tx][i]);
}

#define NB_WIH  6144    // 3*HH*EE / 256
#define NB_WHH 12288    // 3*HH*HH / 256
#define NB_WA   1024    // (HH/32)*(HH/32)
#define NB_WOUT 64000   // (VV/32)*(KOUT/32)
#define NB_CONV (NB_WIH + NB_WHH + NB_WA + NB_WOUT)

__global__ __launch_bounds__(256)
void convert_all(const float* __restrict__ W_ih, const float* __restrict__ W_hh,
                 const float* __restrict__ W_a,  const float* __restrict__ W_out)
{
    int b = blockIdx.x, tid = threadIdx.x;
    if (b < NB_WIH) {
        esplit_blk(W_ih, g_Wih, EE, b, tid);
    } else if (b < NB_WIH + NB_WHH) {
        esplit_blk(W_hh, g_Whh, HH, b - NB_WIH, tid);
    } else if (b < NB_WIH + NB_WHH + NB_WA) {
        int bi = b - NB_WIH - NB_WHH;
        tsplit_blk(W_a, g_Wa, HH, HH, bi % 32, bi / 32, tid);
    } else {
        int bi = b - NB_WIH - NB_WHH - NB_WA;
        tsplit_blk(W_out, g_Wout, KOUT, VV, bi % (VV / 32), bi / (VV / 32), tid);
    }
}

// ======================= init kernels ======================================
__global__ void build_init(const float* __restrict__ latent,
                           const int* __restrict__ style,
                           const float* __restrict__ style_emb,
                           const float* __restrict__ emb)
{
    int idx = blockIdx.x * blockDim.x + threadIdx.x;
    if (idx < BB * 192) {
        int b = idx / 192, k = idx - b * 192;
        g_a0[idx] = (k < 128) ? latent[b * 128 + k]
                              : style_emb[style[b] * 64 + (k - 128)];
    } else {
        int i = idx - BB * 192;
        if (i < BB * EE) {
            int b = i >> 9, e = i & (EE - 1);
            float v = emb[EE /* BOS=1 row */ + e];
            store_act(g_xt, e >> 5, b, e & 31, v);
        }
    }
}

// h = a0 @ W_l2h + b (fp32 FFMA; also emits tiled split-bf16 h)
__global__ __launch_bounds__(128)
void gemm_init(const float* __restrict__ A, int lda,
               const float* __restrict__ Bm, const float* __restrict__ bias,
               float* __restrict__ C, int N, int K)
{
    __shared__ float As[16][68];
    __shared__ float Bs[16][132];
    const int tid = threadIdx.x;
    const int n0 = blockIdx.x * 128;
    const int tm = (tid >> 4) << 3, tn = (tid & 15) << 3;
    float acc[8][8] = {};
    for (int k0 = 0; k0 < K; k0 += 16) {
        {
            int k = tid & 15, m = tid >> 4;
#pragma unroll
            for (int i = 0; i < 8; i++)
                As[k][m + i * 8] = A[(m + i * 8) * lda + k0 + k];
        }
        {
            int w = tid >> 5, n4 = (tid & 31) << 2;
#pragma unroll
            for (int kb = 0; kb < 4; kb++) {
                int k = kb * 4 + w;
                *reinterpret_cast<float4*>(&Bs[k][n4]) =
                    *reinterpret_cast<const float4*>(&Bm[(size_t)(k0 + k) * N + n0 + n4]);
            }
        }
        __syncthreads();
#pragma unroll
        for (int kk = 0; kk < 16; kk++) {
#pragma unroll
            for (int i = 0; i < 8; i++) {
                float a = As[kk][tm + i];
#pragma unroll
                for (int j = 0; j < 8; j++) acc[i][j] += a * Bs[kk][tn + j];
            }
        }
        __syncthreads();
    }
#pragma unroll
    for (int i = 0; i < 8; i++)
#pragma unroll
        for (int j = 0; j < 8; j++) {
            int n = n0 + tn + j;
            float v = acc[i][j] + (bias ? bias[n] : 0.f);
            int m = tm + i;
            C[(size_t)m * N + n] = v;
            store_act(g_ht, n >> 5, m, n & 31, v);
        }
}

// ========================= per-step small kernels ==========================
__global__ void gru_gates(const float* __restrict__ b_ih, const float* __restrict__ b_hh)
{
    int idx = blockIdx.x * blockDim.x + threadIdx.x;   // 64*1024
    if (idx < BB) g_amax[idx] = 0;   // reset fused-argmax slots for this step
    int b = idx >> 10, j = idx & 1023;
    int base = b * 3 * HH + j;
    float ir = b_ih[j], iz = b_ih[j + HH], in = b_ih[j + 2 * HH];
    float hr = b_hh[j], hz = b_hh[j + HH], hn = b_hh[j + 2 * HH];
#pragma unroll
    for (int s = 0; s < 4; s++) {
        ir += g_gip[s][base];
        iz += g_gip[s][base + HH];
        in += g_gip[s][base + 2 * HH];
    }
#pragma unroll
    for (int s = 0; s < 8; s++) {
        hr += g_ghp[s][base];
        hz += g_ghp[s][base + HH];
        hn += g_ghp[s][base + 2 * HH];
    }
    float r = 1.f / (1.f + expf(-(ir + hr)));
    float z = 1.f / (1.f + expf(-(iz + hz)));
    float n = tanhf(in + r * hn);
    float hnew = (1.f - z) * n + z * g_h[idx];
    g_h[idx] = hnew;
    int kc = j >> 5, c = j & 31;
    store_act(g_ht, kc, b, c, hnew);
    store_act(g_vt, kc, b, c, hnew);   // vcat chunks 0..31 = h
}

__global__ __launch_bounds__(512)
void attn_kernel(const float* __restrict__ enc)
{
    int b = blockIdx.x;
    int tid = threadIdx.x;              // 512
    __shared__ float s_q[HH];
    __shared__ float s_scores[TENC];
    __shared__ float s_attn[TENC];

    for (int i = tid; i < HH; i += 512) {
        int o = b * HH + i;
        float q = 0.f;
#pragma unroll
        for (int s = 0; s < 8; s++) q += g_qp[s][o];
        s_q[i] = q;
    }
    __syncthreads();

    int warp = tid >> 5, lane = tid & 31;
    for (int t = warp; t < TENC; t += 16) {
        const float* e = enc + ((size_t)b * TENC + t) * HH;
        float s = 0.f;
        for (int h = lane; h < HH; h += 32) s += s_q[h] * e[h];
#pragma unroll
        for (int o = 16; o; o >>= 1) s += __shfl_xor_sync(0xFFFFFFFFu, s, o);
        if (lane == 0) s_scores[t] = s;
    }
    __syncthreads();

    float mx = -1e30f;
    for (int t = 0; t < TENC; t++) mx = fmaxf(mx, s_scores[t]);
    if (tid < TENC) s_attn[tid] = expf(s_scores[tid] - mx);
    __syncthreads();
    float ssum = 0.f;
    for (int t = 0; t < TENC; t++) ssum += s_attn[t];
    float inv = 1.f / ssum;

    for (int h = tid; h < HH; h += 512) {
        float c = 0.f;
        const float* eb = enc + (size_t)b * TENC * HH + h;
#pragma unroll 8
        for (int t = 0; t < TENC; t++) c += s_attn[t] * eb[(size_t)t * HH];
        c *= inv;
        store_act(g_vt, 32 + (h >> 5), b, h & 31, c);   // vcat chunks 32..63 = ctx
    }
}

// decode g_amax -> token, gather embedding into g_xt
__global__ __launch_bounds__(128)
void embed_next(const float* __restrict__ emb)
{
    int b = blockIdx.x;
    int tid = threadIdx.x;
    int tok = 0x7FFFFFFF - (int)(u32)(g_amax[b] & 0xFFFFFFFFull);
    for (int e = tid; e < EE; e += 128) {
        float v = emb[(size_t)tok * EE + e];
        store_act(g_xt, e >> 5, b, e & 31, v);
    }
}

// ===========================================================================
extern "C" void kernel_launch(void* const* d_in, const int* in_sizes, int n_in,
                              void* d_out, int out_size)
{
    const float* latent    = (const float*)d_in[0];
    const int*   style     = (const int*)  d_in[1];
    const float* enc       = (const float*)d_in[2];
    const float* emb       = (const float*)d_in[4];
    const float* style_emb = (const float*)d_in[5];
    const float* W_l2h     = (const float*)d_in[6];
    const float* b_l2h     = (const float*)d_in[7];
    const float* W_ih      = (const float*)d_in[8];
    const float* W_hh      = (const float*)d_in[9];
    const float* b_ih      = (const float*)d_in[10];
    const float* b_hh      = (const float*)d_in[11];
    const float* W_a       = (const float*)d_in[12];
    const float* W_out     = (const float*)d_in[13];
    const float* b_out     = (const float*)d_in[14];
    float* out = (float*)d_out;

    cudaFuncSetAttribute(gemm_logits, cudaFuncAttributeMaxDynamicSharedMemorySize, GM_SMEM);
    cudaFuncSetAttribute(gemm_q,      cudaFuncAttributeMaxDynamicSharedMemorySize, GM_SMEM);
    cudaFuncSetAttribute(gemm_gigh,   cudaFuncAttributeMaxDynamicSharedMemorySize, GM_SMEM);

    __nv_bfloat16 *pWih, *pWhh, *pWa, *pWout, *pxt, *pht, *pvt;
    float *p_a0, *p_h;
    cudaGetSymbolAddress((void**)&pWih,  g_Wih);
    cudaGetSymbolAddress((void**)&pWhh,  g_Whh);
    cudaGetSymbolAddress((void**)&pWa,   g_Wa);
    cudaGetSymbolAddress((void**)&pWout, g_Wout);
    cudaGetSymbolAddress((void**)&pxt,   g_xt);
    cudaGetSymbolAddress((void**)&pht,   g_ht);
    cudaGetSymbolAddress((void**)&pvt,   g_vt);
    cudaGetSymbolAddress((void**)&p_a0,  g_a0);
    cudaGetSymbolAddress((void**)&p_h,   g_h);

    // launch 0: all weight conversion (tiled + swizzled layout)
    convert_all<<<NB_CONV, 256>>>(W_ih, W_hh, W_a, W_out);
    // launch 1: a0 + x0
    build_init<<<(BB * 192 + BB * EE + 255) / 256, 256>>>(latent, style, style_emb, emb);
    // launch 2: h init (+ tiled split)
    gemm_init<<<HH / 128, 128>>>(p_a0, 192, W_l2h, b_l2h, p_h, HH, 192);

    // decode loop
    for (int t = 0; t < STEPS; t++) {
        gemm_gigh<<<288, 544, GM_SMEM>>>(pxt, pWih, pht, pWhh);
        gru_gates<<<(BB * HH) / 256, 256>>>(b_ih, b_hh);
        gemm_q<<<64, 544, GM_SMEM>>>(pht, pWa);
        attn_kernel<<<BB, 512>>>(enc);
        gemm_logits<<<VV / 128, 544, GM_SMEM>>>(pvt, pWout, b_out,
                                                out + (size_t)t * VV, (long)STEPS * VV);
        if (t < STEPS - 1) embed_next<<<BB, 128>>>(emb);
    }
}